// round 7
// baseline (speedup 1.0000x reference)
#include <cuda_runtime.h>
#include <cuda_bf16.h>
#include <math.h>
#include <stdint.h>

// ---------------- problem constants (fixed by the reference module) ----------
#define NB    4
#define LQ    5440
#define CCH   256
#define NH    8
#define NL    4
#define NP    4
#define DH    32
#define LEN_IN 5440
#define MROWS (NB * LQ)     // 21760 = 170 * 128
#define QPB   4
#define K3    (3 * CCH)     // 768  : [t0|t0|t1] x [s0|s1|s0]
#define K6    (6 * CCH)     // 1536 : [t0|t0|t0|t1|t1|t2] x [s0|s1|s2|s0|s1|s0]

// ---------------- scratch (no allocations allowed) ---------------------------
__device__ float g_value[(size_t)MROWS * CCH];
__device__ float g_off  [(size_t)MROWS * CCH];
__device__ float g_attn [(size_t)MROWS * 128];
__device__ float g_samp [(size_t)MROWS * CCH];

__device__ __nv_bfloat16 g_Aval3[(size_t)MROWS * K3];   // split3(input_flatten)
__device__ __nv_bfloat16 g_Aq6  [(size_t)MROWS * K6];   // split6(query)
__device__ __nv_bfloat16 g_As3  [(size_t)MROWS * K3];   // split3(g_samp)
__device__ __nv_bfloat16 g_Btv3 [(size_t)CCH * K3];     // split3-T(w_val)
__device__ __nv_bfloat16 g_Bto6 [(size_t)CCH * K6];     // split6-T(w_off)
__device__ __nv_bfloat16 g_Bta6 [(size_t)128 * K6];     // split6-T(w_attn)
__device__ __nv_bfloat16 g_Btw3 [(size_t)CCH * K3];     // split3-T(w_out)

// ---------------- fp32 -> bf16 multi-term splits ------------------------------
__device__ __forceinline__ void bf16_split3(float x, __nv_bfloat16& t0,
                                            __nv_bfloat16& t1, __nv_bfloat16& t2)
{
    t0 = __float2bfloat16(x);
    const float r1 = x - __bfloat162float(t0);
    t1 = __float2bfloat16(r1);
    t2 = __float2bfloat16(r1 - __bfloat162float(t1));
}

// A3[M][3K] = [t0 | t0 | t1]
__global__ __launch_bounds__(256)
void splitA3_kernel(const float* __restrict__ X, __nv_bfloat16* __restrict__ A3,
                    int total, int K)
{
    int idx = blockIdx.x * 256 + threadIdx.x;
    if (idx >= total) return;
    const int m = idx / K;
    const int k = idx - m * K;
    __nv_bfloat16 t0, t1, t2;
    bf16_split3(X[idx], t0, t1, t2);
    __nv_bfloat16* row = A3 + (size_t)m * (3 * K);
    row[k] = t0; row[K + k] = t0; row[2 * K + k] = t1;
}

// B3t[N][3K] = [s0 | s1 | s0]
__global__ __launch_bounds__(256)
void splitB3_kernel(const float* __restrict__ W, __nv_bfloat16* __restrict__ B3t,
                    int K, int Nn)
{
    int idx = blockIdx.x * 256 + threadIdx.x;
    if (idx >= K * Nn) return;
    const int k = idx / Nn;
    const int n = idx - k * Nn;
    __nv_bfloat16 s0, s1, s2;
    bf16_split3(W[idx], s0, s1, s2);
    __nv_bfloat16* row = B3t + (size_t)n * (3 * K);
    row[k] = s0; row[K + k] = s1; row[2 * K + k] = s0;
}

// A6[M][6K] = [t0 | t0 | t0 | t1 | t1 | t2]
__global__ __launch_bounds__(256)
void splitA6_kernel(const float* __restrict__ X, __nv_bfloat16* __restrict__ A6,
                    int total, int K)
{
    int idx = blockIdx.x * 256 + threadIdx.x;
    if (idx >= total) return;
    const int m = idx / K;
    const int k = idx - m * K;
    __nv_bfloat16 t0, t1, t2;
    bf16_split3(X[idx], t0, t1, t2);
    __nv_bfloat16* row = A6 + (size_t)m * (6 * K);
    row[k]         = t0; row[K + k]     = t0; row[2 * K + k] = t0;
    row[3 * K + k] = t1; row[4 * K + k] = t1; row[5 * K + k] = t2;
}

// B6t[N][6K] = [s0 | s1 | s2 | s0 | s1 | s0]
__global__ __launch_bounds__(256)
void splitB6_kernel(const float* __restrict__ W, __nv_bfloat16* __restrict__ B6t,
                    int K, int Nn)
{
    int idx = blockIdx.x * 256 + threadIdx.x;
    if (idx >= K * Nn) return;
    const int k = idx / Nn;
    const int n = idx - k * Nn;
    __nv_bfloat16 s0, s1, s2;
    bf16_split3(W[idx], s0, s1, s2);
    __nv_bfloat16* row = B6t + (size_t)n * (6 * K);
    row[k]         = s0; row[K + k]     = s1; row[2 * K + k] = s2;
    row[3 * K + k] = s0; row[4 * K + k] = s1; row[5 * K + k] = s0;
}

// ---------------- bf16 split tensor-core GEMM --------------------------------
// C[M][Nn] = A[M][kext] * Bt[Nn][kext]^T + bias ; 128x128 tile, 8 warps.
#define GBK    16
#define GPITCH 24          // 16 + 8 pad (bf16 elements)

__global__ __launch_bounds__(256)
void gemm_bf16s(int Nn, int kext,
                const __nv_bfloat16* __restrict__ A,
                const __nv_bfloat16* __restrict__ Bt,
                const float* __restrict__ bias,
                float* __restrict__ C)
{
    __shared__ __nv_bfloat16 As[2][128 * GPITCH];
    __shared__ __nv_bfloat16 Bs[2][128 * GPITCH];

    const int kSteps = kext / GBK;
    const int m0 = blockIdx.y * 128;
    const int n0 = blockIdx.x * 128;
    const int tid  = threadIdx.x;
    const int wid  = tid >> 5;
    const int lane = tid & 31;
    const int wm = (wid >> 2) * 64;   // warp m offset (0/64)
    const int wn = (wid & 3) * 32;    // warp n offset (0/32/64/96)
    const int gid = lane >> 2;
    const int tig = lane & 3;

    const int lrow  = tid >> 1;
    const int lhalf = tid & 1;
    const __nv_bfloat16* gA = A  + (size_t)(m0 + lrow) * kext + lhalf * 8;
    const __nv_bfloat16* gB = Bt + (size_t)(n0 + lrow) * kext + lhalf * 8;
    const int sofs = lrow * GPITCH + lhalf * 8;

    float c[4][4][4];
    #pragma unroll
    for (int mi = 0; mi < 4; mi++)
        #pragma unroll
        for (int ni = 0; ni < 4; ni++)
            #pragma unroll
            for (int r = 0; r < 4; r++) c[mi][ni][r] = 0.0f;

    uint4 aPf = *reinterpret_cast<const uint4*>(gA);
    uint4 bPf = *reinterpret_cast<const uint4*>(gB);
    *reinterpret_cast<uint4*>(&As[0][sofs]) = aPf;
    *reinterpret_cast<uint4*>(&Bs[0][sofs]) = bPf;
    __syncthreads();

    for (int kt = 0; kt < kSteps; kt++) {
        const int s = kt & 1;
        if (kt + 1 < kSteps) {
            aPf = *reinterpret_cast<const uint4*>(gA + (kt + 1) * GBK);
            bPf = *reinterpret_cast<const uint4*>(gB + (kt + 1) * GBK);
        }

        uint32_t afr[4][4], bfr[4][2];
        #pragma unroll
        for (int mi = 0; mi < 4; mi++) {
            const int base = (wm + mi * 16 + gid) * GPITCH;
            afr[mi][0] = *reinterpret_cast<const uint32_t*>(&As[s][base + tig * 2]);
            afr[mi][1] = *reinterpret_cast<const uint32_t*>(&As[s][base + 8 * GPITCH + tig * 2]);
            afr[mi][2] = *reinterpret_cast<const uint32_t*>(&As[s][base + tig * 2 + 8]);
            afr[mi][3] = *reinterpret_cast<const uint32_t*>(&As[s][base + 8 * GPITCH + tig * 2 + 8]);
        }
        #pragma unroll
        for (int ni = 0; ni < 4; ni++) {
            const int base = (wn + ni * 8 + gid) * GPITCH;
            bfr[ni][0] = *reinterpret_cast<const uint32_t*>(&Bs[s][base + tig * 2]);
            bfr[ni][1] = *reinterpret_cast<const uint32_t*>(&Bs[s][base + tig * 2 + 8]);
        }

        #pragma unroll
        for (int mi = 0; mi < 4; mi++)
            #pragma unroll
            for (int ni = 0; ni < 4; ni++) {
                asm volatile(
                    "mma.sync.aligned.m16n8k16.row.col.f32.bf16.bf16.f32 "
                    "{%0,%1,%2,%3}, {%4,%5,%6,%7}, {%8,%9}, {%0,%1,%2,%3};"
                    : "+f"(c[mi][ni][0]), "+f"(c[mi][ni][1]),
                      "+f"(c[mi][ni][2]), "+f"(c[mi][ni][3])
                    : "r"(afr[mi][0]), "r"(afr[mi][1]),
                      "r"(afr[mi][2]), "r"(afr[mi][3]),
                      "r"(bfr[ni][0]), "r"(bfr[ni][1]));
            }

        if (kt + 1 < kSteps) {
            *reinterpret_cast<uint4*>(&As[s ^ 1][sofs]) = aPf;
            *reinterpret_cast<uint4*>(&Bs[s ^ 1][sofs]) = bPf;
        }
        __syncthreads();
    }

    #pragma unroll
    for (int mi = 0; mi < 4; mi++) {
        const int row = m0 + wm + mi * 16 + gid;
        #pragma unroll
        for (int ni = 0; ni < 4; ni++) {
            const int col = n0 + wn + ni * 8 + tig * 2;
            const float b0 = bias[col], b1 = bias[col + 1];
            float2 v0 = make_float2(c[mi][ni][0] + b0, c[mi][ni][1] + b1);
            float2 v1 = make_float2(c[mi][ni][2] + b0, c[mi][ni][3] + b1);
            *reinterpret_cast<float2*>(&C[(size_t)row * Nn + col])       = v0;
            *reinterpret_cast<float2*>(&C[(size_t)(row + 8) * Nn + col]) = v1;
        }
    }
}

// ---------------- sampling: two-phase, 4 queries per block (unchanged) -------
__global__ __launch_bounds__(256)
void sample_kernel(const float* __restrict__ refp,
                   float* __restrict__ samp)
{
    const int nq0 = blockIdx.x * QPB;
    const int tid = threadIdx.x;

    __shared__ float4 s_w[QPB * 128];
    __shared__ int4   s_t[QPB * 128];

    #pragma unroll
    for (int rep = 0; rep < 2; rep++) {
        const int task = tid + rep * 256;
        const int q    = task >> 7;
        const int rest = task & 127;
        const int h    = rest >> 4;
        const int i    = rest & 15;
        const int l    = i >> 2;
        const int nq   = nq0 + q;

        float logit = g_attn[(size_t)nq * 128 + rest];
        float mx = logit;
        #pragma unroll
        for (int m = 8; m; m >>= 1)
            mx = fmaxf(mx, __shfl_xor_sync(0xffffffffu, mx, m, 16));
        float e = __expf(logit - mx);
        float ssum = e;
        #pragma unroll
        for (int m = 8; m; m >>= 1)
            ssum += __shfl_xor_sync(0xffffffffu, ssum, m, 16);
        const float aw = e * (1.0f / ssum);

        const int W  = 64 >> l;
        const int S0 = (16384 - (16384 >> (2 * l))) / 3;

        const float2 off = *reinterpret_cast<const float2*>(
            &g_off[(size_t)nq * CCH + rest * 2]);
        const float2 rp  = *reinterpret_cast<const float2*>(
            &refp[((size_t)nq * NL + l) * 2]);

        const float locx = fminf(fmaxf(rp.x + off.x, 0.0f), 1.0f);
        const float locy = fminf(fmaxf(rp.y + off.y, 0.0f), 1.0f);
        const float x = locx * (float)W - 0.5f;
        const float y = locy * (float)W - 0.5f;
        const int xf = (int)floorf(x);
        const int yf = (int)floorf(y);
        const int x0i = min(max(xf,     0), W - 1);
        const int x1i = min(max(xf + 1, 0), W - 1);
        const int y0i = min(max(yf,     0), W - 1);
        const int y1i = min(max(yf + 1, 0), W - 1);
        const float wx1 = (float)x1i - x;
        const float wx0 = x - (float)x0i;
        const float wy1 = (float)y1i - y;
        const float wy0 = y - (float)y0i;

        s_w[task] = make_float4(wx1 * wy1 * aw, wx1 * wy0 * aw,
                                wx0 * wy1 * aw, wx0 * wy0 * aw);
        s_t[task] = make_int4(S0 + y0i * W + x0i,
                              S0 + y1i * W + x0i,
                              S0 + y0i * W + x1i,
                              S0 + y1i * W + x1i);
    }
    __syncthreads();

    const int q  = tid >> 6;
    const int r  = tid & 63;
    const int h  = r >> 3;
    const int d4 = r & 7;
    const int nq = nq0 + q;
    const int n  = nq / LQ;

    const float4* vbase = reinterpret_cast<const float4*>(
        g_value + (size_t)n * LEN_IN * CCH + h * DH + d4 * 4);

    float4 acc = make_float4(0.0f, 0.0f, 0.0f, 0.0f);
    const int tb0 = q * 128 + h * 16;

    #pragma unroll
    for (int i = 0; i < 16; i++) {
        const float4 w  = s_w[tb0 + i];
        const int4   tt = s_t[tb0 + i];
        const float4 va = vbase[(size_t)tt.x * (CCH / 4)];
        const float4 vb = vbase[(size_t)tt.y * (CCH / 4)];
        const float4 vc = vbase[(size_t)tt.z * (CCH / 4)];
        const float4 vd = vbase[(size_t)tt.w * (CCH / 4)];
        acc.x += w.x * va.x + w.y * vb.x + w.z * vc.x + w.w * vd.x;
        acc.y += w.x * va.y + w.y * vb.y + w.z * vc.y + w.w * vd.y;
        acc.z += w.x * va.z + w.y * vb.z + w.z * vc.z + w.w * vd.z;
        acc.w += w.x * va.w + w.y * vb.w + w.z * vc.w + w.w * vd.w;
    }

    *reinterpret_cast<float4*>(&samp[(size_t)nq * CCH + h * DH + d4 * 4]) = acc;
}

// ---------------- launch ------------------------------------------------------
extern "C" void kernel_launch(void* const* d_in, const int* in_sizes, int n_in,
                              void* d_out, int out_size)
{
    const float* query  = (const float*)d_in[0];
    const float* refp   = (const float*)d_in[1];
    const float* inputf = (const float*)d_in[2];
    const float* w_off  = (const float*)d_in[5];
    const float* b_off  = (const float*)d_in[6];
    const float* w_attn = (const float*)d_in[7];
    const float* b_attn = (const float*)d_in[8];
    const float* w_val  = (const float*)d_in[9];
    const float* b_val  = (const float*)d_in[10];
    const float* w_out  = (const float*)d_in[11];
    const float* b_out  = (const float*)d_in[12];
    float* out = (float*)d_out;

    float *gv, *go, *ga, *gs;
    cudaGetSymbolAddress((void**)&gv, g_value);
    cudaGetSymbolAddress((void**)&go, g_off);
    cudaGetSymbolAddress((void**)&ga, g_attn);
    cudaGetSymbolAddress((void**)&gs, g_samp);
    __nv_bfloat16 *aval3, *aq6, *as3, *btv3, *bto6, *bta6, *btw3;
    cudaGetSymbolAddress((void**)&aval3, g_Aval3);
    cudaGetSymbolAddress((void**)&aq6,   g_Aq6);
    cudaGetSymbolAddress((void**)&as3,   g_As3);
    cudaGetSymbolAddress((void**)&btv3,  g_Btv3);
    cudaGetSymbolAddress((void**)&bto6,  g_Bto6);
    cudaGetSymbolAddress((void**)&bta6,  g_Bta6);
    cudaGetSymbolAddress((void**)&btw3,  g_Btw3);

    const int MK = MROWS * CCH;
    const dim3 blk(256);
    const dim3 gSplitA((MK + 255) / 256);
    const dim3 gSplitB256((CCH * CCH + 255) / 256);
    const dim3 gSplitB128((CCH * 128 + 255) / 256);
    const dim3 gGemm256(CCH / 128, MROWS / 128);   // (2, 170)
    const dim3 gGemm128(1, MROWS / 128);           // (1, 170)

    // weight splits
    splitB3_kernel<<<gSplitB256, blk>>>(w_val,  btv3, CCH, CCH);
    splitB6_kernel<<<gSplitB256, blk>>>(w_off,  bto6, CCH, CCH);
    splitB6_kernel<<<gSplitB128, blk>>>(w_attn, bta6, CCH, 128);
    splitB3_kernel<<<gSplitB256, blk>>>(w_out,  btw3, CCH, CCH);
    // activation splits
    splitA3_kernel<<<gSplitA, blk>>>(inputf, aval3, MK, CCH);
    splitA6_kernel<<<gSplitA, blk>>>(query,  aq6,   MK, CCH);

    // value = input_flatten @ w_val + b_val        (bf16x3)
    gemm_bf16s<<<gGemm256, blk>>>(CCH, K3, aval3, btv3, b_val, gv);
    // off = query @ w_off + b_off                  (bf16x6, coordinate-critical)
    gemm_bf16s<<<gGemm256, blk>>>(CCH, K6, aq6, bto6, b_off, go);
    // attn logits = query @ w_attn + b_attn        (bf16x6, shares A split)
    gemm_bf16s<<<gGemm128, blk>>>(128, K6, aq6, bta6, b_attn, ga);
    // sampling
    sample_kernel<<<MROWS / QPB, blk>>>(refp, gs);
    // out = samp @ w_out + b_out                   (bf16x3)
    splitA3_kernel<<<gSplitA, blk>>>(gs, as3, MK, CCH);
    gemm_bf16s<<<gGemm256, blk>>>(CCH, K3, as3, btw3, b_out, out);
}

// round 8
// speedup vs baseline: 1.1636x; 1.1636x over previous
#include <cuda_runtime.h>
#include <cuda_bf16.h>
#include <math.h>
#include <stdint.h>

// ---------------- problem constants ----------------
#define NB    4
#define LQ    5440
#define CCH   256
#define NH    8
#define NL    4
#define NP    4
#define DH    32
#define LEN_IN 5440
#define MROWS (NB * LQ)     // 21760
#define QPB   4
#define K3    (3 * CCH)     // 768  physical split storage [t0|t1|t2]
#define KLOG  (6 * CCH)     // 1536 logical K of the x6 product schedule

// ---------------- scratch ----------------
__device__ float g_value[(size_t)MROWS * CCH];
__device__ float g_off  [(size_t)MROWS * CCH];
__device__ float g_attn [(size_t)MROWS * 128];

__device__ __nv_bfloat16 g_Ain[(size_t)MROWS * K3];   // split3(input_flatten)
__device__ __nv_bfloat16 g_Aq [(size_t)MROWS * K3];   // split3(query)
__device__ __nv_bfloat16 g_As [(size_t)MROWS * K3];   // split3(sampled)
__device__ __nv_bfloat16 g_Btv[(size_t)CCH * K3];
__device__ __nv_bfloat16 g_Bto[(size_t)CCH * K3];
__device__ __nv_bfloat16 g_Bta[(size_t)128 * K3];
__device__ __nv_bfloat16 g_Btw[(size_t)CCH * K3];

// segment remap for the x6 product schedule:
// logical seg s: A uses t[c_amap[s]], B uses s[c_bmap[s]]
// products: t0s0 t0s1 t0s2 t1s0 t1s1 t2s0  (dropped terms ~2^-26)
__device__ __constant__ int c_amap[6] = {0, 0, 0, 1, 1, 2};
__device__ __constant__ int c_bmap[6] = {0, 1, 2, 0, 1, 0};

// ---------------- fp32 -> 3-term bf16 split ----------------
__device__ __forceinline__ void bf16_split3(float x, __nv_bfloat16& t0,
                                            __nv_bfloat16& t1, __nv_bfloat16& t2)
{
    t0 = __float2bfloat16(x);
    const float r1 = x - __bfloat162float(t0);
    t1 = __float2bfloat16(r1);
    t2 = __float2bfloat16(r1 - __bfloat162float(t1));
}

// A[m][k] (K=256) -> A3 row m: [t0|t1|t2]
__global__ __launch_bounds__(256)
void splitA_kernel(const float* __restrict__ X, __nv_bfloat16* __restrict__ A3)
{
    const int idx = blockIdx.x * 256 + threadIdx.x;   // < MROWS*256
    const int m = idx >> 8;
    const int k = idx & 255;
    __nv_bfloat16 t0, t1, t2;
    bf16_split3(X[idx], t0, t1, t2);
    __nv_bfloat16* row = A3 + (size_t)m * K3;
    row[k] = t0; row[CCH + k] = t1; row[2 * CCH + k] = t2;
}

__device__ __forceinline__ void splitB_body(const float* W, __nv_bfloat16* B3t,
                                            int Nn, int e)
{
    const int k = e / Nn;
    const int n = e - k * Nn;
    __nv_bfloat16 s0, s1, s2;
    bf16_split3(W[e], s0, s1, s2);
    __nv_bfloat16* row = B3t + (size_t)n * K3;
    row[k] = s0; row[CCH + k] = s1; row[2 * CCH + k] = s2;
}

// all four weight splits in one launch
__global__ __launch_bounds__(256)
void split_weights(const float* __restrict__ wv, const float* __restrict__ wo,
                   const float* __restrict__ wa, const float* __restrict__ ww)
{
    const int b = blockIdx.x;
    const int t = threadIdx.x;
    if (b < 256)      splitB_body(wv, g_Btv, CCH, (b)       * 256 + t);
    else if (b < 512) splitB_body(wo, g_Bto, CCH, (b - 256) * 256 + t);
    else if (b < 640) splitB_body(wa, g_Bta, 128, (b - 512) * 256 + t);
    else              splitB_body(ww, g_Btw, CCH, (b - 640) * 256 + t);
}

// ---------------- bf16x6 tensor-core GEMM, cp.async 4-stage -------------------
#define GBK    32
#define GP     40                  // pitch: rows hit all 32 banks once
#define STAGES 4
#define OPELTS (128 * GP)          // elements per stage per operand
#define KSTEPS (KLOG / GBK)        // 48
#define GSMEM  (STAGES * 2 * OPELTS * 2)   // 81920 bytes

#define CP16(sm, gp) asm volatile( \
    "cp.async.cg.shared.global [%0], [%1], 16;" :: "r"(sm), "l"(gp))
#define CP_COMMIT()  asm volatile("cp.async.commit_group;")
#define CP_WAIT2()   asm volatile("cp.async.wait_group 2;")

__global__ __launch_bounds__(256)
void gemm_bf16x6(int Nn,
                 const __nv_bfloat16* __restrict__ A,    // [M][K3] physical
                 const __nv_bfloat16* __restrict__ Bt,   // [Nn][K3] physical
                 const float* __restrict__ bias,
                 float* __restrict__ C)
{
    extern __shared__ __nv_bfloat16 sm[];
    __nv_bfloat16* As = sm;                    // [STAGES][OPELTS]
    __nv_bfloat16* Bs = sm + STAGES * OPELTS;

    const int m0 = blockIdx.y * 128;
    const int n0 = blockIdx.x * 128;
    const int tid  = threadIdx.x;
    const int wid  = tid >> 5;
    const int lane = tid & 31;
    const int wm = (wid >> 2) * 64;
    const int wn = (wid & 3) * 32;
    const int gid = lane >> 3;  // dummy init fixed below
    (void)gid;
    const int g8  = lane >> 2;      // 0..7
    const int tig = lane & 3;       // 0..3

    // loader: thread handles rows lrow and lrow+64, 8-bf16 segment lseg
    const int lrow = tid >> 2;      // 0..63
    const int lseg = tid & 3;       // 0..3
    const __nv_bfloat16* gA0 = A  + (size_t)(m0 + lrow)      * K3 + lseg * 8;
    const __nv_bfloat16* gA1 = A  + (size_t)(m0 + lrow + 64) * K3 + lseg * 8;
    const __nv_bfloat16* gB0 = Bt + (size_t)(n0 + lrow)      * K3 + lseg * 8;
    const __nv_bfloat16* gB1 = Bt + (size_t)(n0 + lrow + 64) * K3 + lseg * 8;
    const uint32_t sA0 = (uint32_t)__cvta_generic_to_shared(
        &As[lrow * GP + lseg * 8]);
    const uint32_t sB0 = (uint32_t)__cvta_generic_to_shared(
        &Bs[lrow * GP + lseg * 8]);

    float c[4][4][4];
    #pragma unroll
    for (int mi = 0; mi < 4; mi++)
        #pragma unroll
        for (int ni = 0; ni < 4; ni++)
            #pragma unroll
            for (int r = 0; r < 4; r++) c[mi][ni][r] = 0.0f;

    // stage loader with x6->x3 segment remap
    auto load_stage = [&](int st) {
        const int slot = st & (STAGES - 1);
        const int k0   = st * GBK;              // logical k in [0, 1536)
        const int seg  = k0 >> 8;               // logical 256-segment
        const int ka   = c_amap[seg] * CCH + (k0 & 255);
        const int kb   = c_bmap[seg] * CCH + (k0 & 255);
        const uint32_t so = slot * OPELTS * 2;  // byte offset
        CP16(sA0 + so,              gA0 + ka);
        CP16(sA0 + so + 64 * GP * 2, gA1 + ka);
        CP16(sB0 + so,              gB0 + kb);
        CP16(sB0 + so + 64 * GP * 2, gB1 + kb);
    };

    load_stage(0); CP_COMMIT();
    load_stage(1); CP_COMMIT();
    load_stage(2); CP_COMMIT();

    for (int kt = 0; kt < KSTEPS; kt++) {
        CP_WAIT2();
        __syncthreads();
        const __nv_bfloat16* Asl = As + (kt & (STAGES - 1)) * OPELTS;
        const __nv_bfloat16* Bsl = Bs + (kt & (STAGES - 1)) * OPELTS;

        #pragma unroll
        for (int h = 0; h < 2; h++) {
            uint32_t afr[4][4], bfr[4][2];
            #pragma unroll
            for (int mi = 0; mi < 4; mi++) {
                const int rb = (wm + mi * 16 + g8) * GP + h * 16 + tig * 2;
                afr[mi][0] = *reinterpret_cast<const uint32_t*>(&Asl[rb]);
                afr[mi][1] = *reinterpret_cast<const uint32_t*>(&Asl[rb + 8 * GP]);
                afr[mi][2] = *reinterpret_cast<const uint32_t*>(&Asl[rb + 8]);
                afr[mi][3] = *reinterpret_cast<const uint32_t*>(&Asl[rb + 8 * GP + 8]);
            }
            #pragma unroll
            for (int ni = 0; ni < 4; ni++) {
                const int rb = (wn + ni * 8 + g8) * GP + h * 16 + tig * 2;
                bfr[ni][0] = *reinterpret_cast<const uint32_t*>(&Bsl[rb]);
                bfr[ni][1] = *reinterpret_cast<const uint32_t*>(&Bsl[rb + 8]);
            }
            #pragma unroll
            for (int mi = 0; mi < 4; mi++)
                #pragma unroll
                for (int ni = 0; ni < 4; ni++) {
                    asm volatile(
                        "mma.sync.aligned.m16n8k16.row.col.f32.bf16.bf16.f32 "
                        "{%0,%1,%2,%3}, {%4,%5,%6,%7}, {%8,%9}, {%0,%1,%2,%3};"
                        : "+f"(c[mi][ni][0]), "+f"(c[mi][ni][1]),
                          "+f"(c[mi][ni][2]), "+f"(c[mi][ni][3])
                        : "r"(afr[mi][0]), "r"(afr[mi][1]),
                          "r"(afr[mi][2]), "r"(afr[mi][3]),
                          "r"(bfr[ni][0]), "r"(bfr[ni][1]));
                }
        }

        if (kt + STAGES - 1 < KSTEPS) load_stage(kt + STAGES - 1);
        CP_COMMIT();
    }

    #pragma unroll
    for (int mi = 0; mi < 4; mi++) {
        const int row = m0 + wm + mi * 16 + g8;
        #pragma unroll
        for (int ni = 0; ni < 4; ni++) {
            const int col = n0 + wn + ni * 8 + tig * 2;
            const float b0 = bias[col], b1 = bias[col + 1];
            float2 v0 = make_float2(c[mi][ni][0] + b0, c[mi][ni][1] + b1);
            float2 v1 = make_float2(c[mi][ni][2] + b0, c[mi][ni][3] + b1);
            *reinterpret_cast<float2*>(&C[(size_t)row * Nn + col])       = v0;
            *reinterpret_cast<float2*>(&C[(size_t)(row + 8) * Nn + col]) = v1;
        }
    }
}

// ---------------- sampling (two-phase) + fused split of its output -----------
__global__ __launch_bounds__(256)
void sample_kernel(const float* __restrict__ refp)
{
    const int nq0 = blockIdx.x * QPB;
    const int tid = threadIdx.x;

    __shared__ float4 s_w[QPB * 128];
    __shared__ int4   s_t[QPB * 128];

    #pragma unroll
    for (int rep = 0; rep < 2; rep++) {
        const int task = tid + rep * 256;
        const int q    = task >> 7;
        const int rest = task & 127;
        const int l    = (rest & 15) >> 2;
        const int nq   = nq0 + q;

        float logit = g_attn[(size_t)nq * 128 + rest];
        float mx = logit;
        #pragma unroll
        for (int m = 8; m; m >>= 1)
            mx = fmaxf(mx, __shfl_xor_sync(0xffffffffu, mx, m, 16));
        float e = __expf(logit - mx);
        float ssum = e;
        #pragma unroll
        for (int m = 8; m; m >>= 1)
            ssum += __shfl_xor_sync(0xffffffffu, ssum, m, 16);
        const float aw = e * (1.0f / ssum);

        const int W  = 64 >> l;
        const int S0 = (16384 - (16384 >> (2 * l))) / 3;

        const float2 off = *reinterpret_cast<const float2*>(
            &g_off[(size_t)nq * CCH + rest * 2]);
        const float2 rp  = *reinterpret_cast<const float2*>(
            &refp[((size_t)nq * NL + l) * 2]);

        const float locx = fminf(fmaxf(rp.x + off.x, 0.0f), 1.0f);
        const float locy = fminf(fmaxf(rp.y + off.y, 0.0f), 1.0f);
        const float x = locx * (float)W - 0.5f;
        const float y = locy * (float)W - 0.5f;
        const int xf = (int)floorf(x);
        const int yf = (int)floorf(y);
        const int x0i = min(max(xf,     0), W - 1);
        const int x1i = min(max(xf + 1, 0), W - 1);
        const int y0i = min(max(yf,     0), W - 1);
        const int y1i = min(max(yf + 1, 0), W - 1);
        const float wx1 = (float)x1i - x;
        const float wx0 = x - (float)x0i;
        const float wy1 = (float)y1i - y;
        const float wy0 = y - (float)y0i;

        s_w[task] = make_float4(wx1 * wy1 * aw, wx1 * wy0 * aw,
                                wx0 * wy1 * aw, wx0 * wy0 * aw);
        s_t[task] = make_int4(S0 + y0i * W + x0i,
                              S0 + y1i * W + x0i,
                              S0 + y0i * W + x1i,
                              S0 + y1i * W + x1i);
    }
    __syncthreads();

    const int q  = tid >> 6;
    const int r  = tid & 63;
    const int h  = r >> 3;
    const int d4 = r & 7;
    const int nq = nq0 + q;
    const int n  = nq / LQ;

    const float4* vbase = reinterpret_cast<const float4*>(
        g_value + (size_t)n * LEN_IN * CCH + h * DH + d4 * 4);

    float4 acc = make_float4(0.0f, 0.0f, 0.0f, 0.0f);
    const int tb0 = q * 128 + h * 16;

    #pragma unroll
    for (int i = 0; i < 16; i++) {
        const float4 w  = s_w[tb0 + i];
        const int4   tt = s_t[tb0 + i];
        const float4 va = vbase[(size_t)tt.x * (CCH / 4)];
        const float4 vb = vbase[(size_t)tt.y * (CCH / 4)];
        const float4 vc = vbase[(size_t)tt.z * (CCH / 4)];
        const float4 vd = vbase[(size_t)tt.w * (CCH / 4)];
        acc.x += w.x * va.x + w.y * vb.x + w.z * vc.x + w.w * vd.x;
        acc.y += w.x * va.y + w.y * vb.y + w.z * vc.y + w.w * vd.y;
        acc.z += w.x * va.z + w.y * vb.z + w.z * vc.z + w.w * vd.z;
        acc.w += w.x * va.w + w.y * vb.w + w.z * vc.w + w.w * vd.w;
    }

    // fused split3 of the sampled output -> g_As (physical [t0|t1|t2])
    __align__(8) __nv_bfloat16 t0[4], t1[4], t2[4];
    const float v4[4] = {acc.x, acc.y, acc.z, acc.w};
    #pragma unroll
    for (int j = 0; j < 4; j++) bf16_split3(v4[j], t0[j], t1[j], t2[j]);

    __nv_bfloat16* row = g_As + (size_t)nq * K3 + h * DH + d4 * 4;
    *reinterpret_cast<ushort4*>(row)             = *reinterpret_cast<ushort4*>(t0);
    *reinterpret_cast<ushort4*>(row + CCH)       = *reinterpret_cast<ushort4*>(t1);
    *reinterpret_cast<ushort4*>(row + 2 * CCH)   = *reinterpret_cast<ushort4*>(t2);
}

// ---------------- launch ------------------------------------------------------
extern "C" void kernel_launch(void* const* d_in, const int* in_sizes, int n_in,
                              void* d_out, int out_size)
{
    const float* query  = (const float*)d_in[0];
    const float* refp   = (const float*)d_in[1];
    const float* inputf = (const float*)d_in[2];
    const float* w_off  = (const float*)d_in[5];
    const float* b_off  = (const float*)d_in[6];
    const float* w_attn = (const float*)d_in[7];
    const float* b_attn = (const float*)d_in[8];
    const float* w_val  = (const float*)d_in[9];
    const float* b_val  = (const float*)d_in[10];
    const float* w_out  = (const float*)d_in[11];
    const float* b_out  = (const float*)d_in[12];
    float* out = (float*)d_out;

    cudaFuncSetAttribute(gemm_bf16x6,
                         cudaFuncAttributeMaxDynamicSharedMemorySize, GSMEM);

    float *gv, *go, *ga;
    cudaGetSymbolAddress((void**)&gv, g_value);
    cudaGetSymbolAddress((void**)&go, g_off);
    cudaGetSymbolAddress((void**)&ga, g_attn);
    __nv_bfloat16 *ain, *aq, *as, *btv, *bto, *bta, *btw;
    cudaGetSymbolAddress((void**)&ain, g_Ain);
    cudaGetSymbolAddress((void**)&aq,  g_Aq);
    cudaGetSymbolAddress((void**)&as,  g_As);
    cudaGetSymbolAddress((void**)&btv, g_Btv);
    cudaGetSymbolAddress((void**)&bto, g_Bto);
    cudaGetSymbolAddress((void**)&bta, g_Bta);
    cudaGetSymbolAddress((void**)&btw, g_Btw);

    const dim3 blk(256);
    const dim3 gSplitA(MROWS);                     // MROWS*256/256
    const dim3 gGemm256(2, MROWS / 128);           // (2, 170)
    const dim3 gGemm128(1, MROWS / 128);           // (1, 170)

    split_weights<<<896, blk>>>(w_val, w_off, w_attn, w_out);
    splitA_kernel<<<gSplitA, blk>>>(inputf, ain);
    splitA_kernel<<<gSplitA, blk>>>(query,  aq);

    gemm_bf16x6<<<gGemm256, blk, GSMEM>>>(CCH, ain, btv, b_val, gv);
    gemm_bf16x6<<<gGemm256, blk, GSMEM>>>(CCH, aq,  bto, b_off, go);
    gemm_bf16x6<<<gGemm128, blk, GSMEM>>>(128, aq,  bta, b_attn, ga);

    sample_kernel<<<MROWS / QPB, blk>>>(refp);

    gemm_bf16x6<<<gGemm256, blk, GSMEM>>>(CCH, as, btw, b_out, out);
}

// round 10
// speedup vs baseline: 1.3802x; 1.1861x over previous
#include <cuda_runtime.h>
#include <cuda_bf16.h>
#include <math.h>
#include <stdint.h>

// ---------------- problem constants ----------------
#define NB    4
#define LQ    5440
#define CCH   256
#define NH    8
#define NL    4
#define NP    4
#define DH    32
#define LEN_IN 5440
#define MROWS (NB * LQ)     // 21760
#define QPB   4
#define K3    (3 * CCH)     // 768 physical split storage [t0|t1|t2]
#define KLOG3 (3 * CCH)     // logical K of the x3 schedule

// ---------------- scratch ----------------
__device__ float g_value[(size_t)MROWS * CCH];
__device__ float g_off  [(size_t)MROWS * CCH];
__device__ float g_attn [(size_t)MROWS * 128];

__device__ __nv_bfloat16 g_Ain[(size_t)MROWS * K3];   // split3(input_flatten)
__device__ __nv_bfloat16 g_As [(size_t)MROWS * K3];   // split(sampled), t0|t1 used
__device__ __nv_bfloat16 g_Btv[(size_t)CCH * K3];
__device__ __nv_bfloat16 g_Btw[(size_t)CCH * K3];

// x3 product schedule: t0s0 + t0s1 + t1s0
__device__ __constant__ int c_amap[3] = {0, 0, 1};
__device__ __constant__ int c_bmap[3] = {0, 1, 0};

// ---------------- fp32 -> bf16 splits ----------------
__device__ __forceinline__ void bf16_split3(float x, __nv_bfloat16& t0,
                                            __nv_bfloat16& t1, __nv_bfloat16& t2)
{
    t0 = __float2bfloat16(x);
    const float r1 = x - __bfloat162float(t0);
    t1 = __float2bfloat16(r1);
    t2 = __float2bfloat16(r1 - __bfloat162float(t1));
}

__global__ __launch_bounds__(256)
void splitA_kernel(const float* __restrict__ X, __nv_bfloat16* __restrict__ A3)
{
    const int idx = blockIdx.x * 256 + threadIdx.x;   // < MROWS*256
    const int m = idx >> 8;
    const int k = idx & 255;
    __nv_bfloat16 t0, t1, t2;
    bf16_split3(X[idx], t0, t1, t2);
    __nv_bfloat16* row = A3 + (size_t)m * K3;
    row[k] = t0; row[CCH + k] = t1; row[2 * CCH + k] = t2;
}

__device__ __forceinline__ void splitB_body(const float* W, __nv_bfloat16* B3t,
                                            int Nn, int e)
{
    const int k = e / Nn;
    const int n = e - k * Nn;
    __nv_bfloat16 s0, s1, s2;
    bf16_split3(W[e], s0, s1, s2);
    __nv_bfloat16* row = B3t + (size_t)n * K3;
    row[k] = s0; row[CCH + k] = s1; row[2 * CCH + k] = s2;
}

// w_val and w_out splits in one launch (off/attn stay fp32 SIMT)
__global__ __launch_bounds__(256)
void split_weights(const float* __restrict__ wv, const float* __restrict__ ww)
{
    const int b = blockIdx.x;
    const int t = threadIdx.x;
    if (b < 256) splitB_body(wv, g_Btv, CCH, b * 256 + t);
    else         splitB_body(ww, g_Btw, CCH, (b - 256) * 256 + t);
}

// ---------------- fp32 SIMT SGEMM (proven exact path) -------------------------
#define BM 128
#define BN 128
#define BK 8
#define TM 8
#define TN 8

__global__ __launch_bounds__(256)
void sgemm_bias(int M, int Nn, int K,
                const float* __restrict__ A,
                const float* __restrict__ B,
                const float* __restrict__ bias,
                float* __restrict__ C)
{
    __shared__ float As[BK * BM];
    __shared__ float Bs[BK * BN];

    const int crow = blockIdx.y;
    const int ccol = blockIdx.x;

    A += (size_t)crow * BM * K;
    B += (size_t)ccol * BN;
    C += (size_t)crow * BM * Nn + (size_t)ccol * BN;
    bias += (size_t)ccol * BN;

    const int tid = threadIdx.x;
    const int threadRow = tid / (BN / TN);
    const int threadCol = tid % (BN / TN);
    const int innerRowA = tid / (BK / 4);
    const int innerColA = tid % (BK / 4);
    const int innerRowB = tid / (BN / 4);
    const int innerColB = tid % (BN / 4);

    float acc[TM * TN] = {0.0f};
    float regM[TM];
    float regN[TN];

    for (int k0 = 0; k0 < K; k0 += BK) {
        float4 a4 = *reinterpret_cast<const float4*>(
            &A[(size_t)innerRowA * K + innerColA * 4]);
        As[(innerColA * 4 + 0) * BM + innerRowA] = a4.x;
        As[(innerColA * 4 + 1) * BM + innerRowA] = a4.y;
        As[(innerColA * 4 + 2) * BM + innerRowA] = a4.z;
        As[(innerColA * 4 + 3) * BM + innerRowA] = a4.w;

        *reinterpret_cast<float4*>(&Bs[innerRowB * BN + innerColB * 4]) =
            *reinterpret_cast<const float4*>(
                &B[(size_t)innerRowB * Nn + innerColB * 4]);

        __syncthreads();
        A += BK;
        B += (size_t)BK * Nn;

        #pragma unroll
        for (int k = 0; k < BK; k++) {
            #pragma unroll
            for (int i = 0; i < TM; i++)
                regM[i] = As[k * BM + threadRow * TM + i];
            #pragma unroll
            for (int j = 0; j < TN; j++)
                regN[j] = Bs[k * BN + threadCol * TN + j];
            #pragma unroll
            for (int i = 0; i < TM; i++)
                #pragma unroll
                for (int j = 0; j < TN; j++)
                    acc[i * TN + j] += regM[i] * regN[j];
        }
        __syncthreads();
    }

    float bj[TN];
    #pragma unroll
    for (int j = 0; j < TN; j++)
        bj[j] = bias[threadCol * TN + j];

    #pragma unroll
    for (int i = 0; i < TM; i++) {
        const int row = threadRow * TM + i;
        #pragma unroll
        for (int j = 0; j < TN; j += 4) {
            const int col = threadCol * TN + j;
            float4 o;
            o.x = acc[i * TN + j + 0] + bj[j + 0];
            o.y = acc[i * TN + j + 1] + bj[j + 1];
            o.z = acc[i * TN + j + 2] + bj[j + 2];
            o.w = acc[i * TN + j + 3] + bj[j + 3];
            *reinterpret_cast<float4*>(&C[(size_t)row * Nn + col]) = o;
        }
    }
}

// ---------------- bf16x3 tensor-core GEMM, cp.async 4-stage -------------------
#define GBK    32
#define GP     40
#define STAGES 4
#define OPELTS (128 * GP)
#define KSTEPS (KLOG3 / GBK)               // 24
#define GSMEM  (STAGES * 2 * OPELTS * 2)   // 81920 bytes

#define CP16(sm_, gp_) asm volatile( \
    "cp.async.cg.shared.global [%0], [%1], 16;" :: "r"(sm_), "l"(gp_))
#define CP_COMMIT()  asm volatile("cp.async.commit_group;")
#define CP_WAIT2()   asm volatile("cp.async.wait_group 2;")

__global__ __launch_bounds__(256)
void gemm_bf16x3(int Nn,
                 const __nv_bfloat16* __restrict__ A,    // [M][K3] physical
                 const __nv_bfloat16* __restrict__ Bt,   // [Nn][K3] physical
                 const float* __restrict__ bias,
                 float* __restrict__ C)
{
    extern __shared__ __nv_bfloat16 sm[];
    __nv_bfloat16* As = sm;
    __nv_bfloat16* Bs = sm + STAGES * OPELTS;

    const int m0 = blockIdx.y * 128;
    const int n0 = blockIdx.x * 128;
    const int tid  = threadIdx.x;
    const int wid  = tid >> 5;
    const int lane = tid & 31;
    const int wm = (wid >> 2) * 64;
    const int wn = (wid & 3) * 32;
    const int g8  = lane >> 2;
    const int tig = lane & 3;

    const int lrow = tid >> 2;
    const int lseg = tid & 3;
    const __nv_bfloat16* gA0 = A  + (size_t)(m0 + lrow)      * K3 + lseg * 8;
    const __nv_bfloat16* gA1 = A  + (size_t)(m0 + lrow + 64) * K3 + lseg * 8;
    const __nv_bfloat16* gB0 = Bt + (size_t)(n0 + lrow)      * K3 + lseg * 8;
    const __nv_bfloat16* gB1 = Bt + (size_t)(n0 + lrow + 64) * K3 + lseg * 8;
    const uint32_t sA0 = (uint32_t)__cvta_generic_to_shared(
        &As[lrow * GP + lseg * 8]);
    const uint32_t sB0 = (uint32_t)__cvta_generic_to_shared(
        &Bs[lrow * GP + lseg * 8]);

    float c[4][4][4];
    #pragma unroll
    for (int mi = 0; mi < 4; mi++)
        #pragma unroll
        for (int ni = 0; ni < 4; ni++)
            #pragma unroll
            for (int r = 0; r < 4; r++) c[mi][ni][r] = 0.0f;

    auto load_stage = [&](int st) {
        const int slot = st & (STAGES - 1);
        const int k0   = st * GBK;
        const int seg  = k0 >> 8;
        const int ka   = c_amap[seg] * CCH + (k0 & 255);
        const int kb   = c_bmap[seg] * CCH + (k0 & 255);
        const uint32_t so = slot * OPELTS * 2;
        CP16(sA0 + so,               gA0 + ka);
        CP16(sA0 + so + 64 * GP * 2, gA1 + ka);
        CP16(sB0 + so,               gB0 + kb);
        CP16(sB0 + so + 64 * GP * 2, gB1 + kb);
    };

    load_stage(0); CP_COMMIT();
    load_stage(1); CP_COMMIT();
    load_stage(2); CP_COMMIT();

    for (int kt = 0; kt < KSTEPS; kt++) {
        CP_WAIT2();
        __syncthreads();
        const __nv_bfloat16* Asl = As + (kt & (STAGES - 1)) * OPELTS;
        const __nv_bfloat16* Bsl = Bs + (kt & (STAGES - 1)) * OPELTS;

        #pragma unroll
        for (int h = 0; h < 2; h++) {
            uint32_t afr[4][4], bfr[4][2];
            #pragma unroll
            for (int mi = 0; mi < 4; mi++) {
                const int rb = (wm + mi * 16 + g8) * GP + h * 16 + tig * 2;
                afr[mi][0] = *reinterpret_cast<const uint32_t*>(&Asl[rb]);
                afr[mi][1] = *reinterpret_cast<const uint32_t*>(&Asl[rb + 8 * GP]);
                afr[mi][2] = *reinterpret_cast<const uint32_t*>(&Asl[rb + 8]);
                afr[mi][3] = *reinterpret_cast<const uint32_t*>(&Asl[rb + 8 * GP + 8]);
            }
            #pragma unroll
            for (int ni = 0; ni < 4; ni++) {
                const int rb = (wn + ni * 8 + g8) * GP + h * 16 + tig * 2;
                bfr[ni][0] = *reinterpret_cast<const uint32_t*>(&Bsl[rb]);
                bfr[ni][1] = *reinterpret_cast<const uint32_t*>(&Bsl[rb + 8]);
            }
            #pragma unroll
            for (int mi = 0; mi < 4; mi++)
                #pragma unroll
                for (int ni = 0; ni < 4; ni++) {
                    asm volatile(
                        "mma.sync.aligned.m16n8k16.row.col.f32.bf16.bf16.f32 "
                        "{%0,%1,%2,%3}, {%4,%5,%6,%7}, {%8,%9}, {%0,%1,%2,%3};"
                        : "+f"(c[mi][ni][0]), "+f"(c[mi][ni][1]),
                          "+f"(c[mi][ni][2]), "+f"(c[mi][ni][3])
                        : "r"(afr[mi][0]), "r"(afr[mi][1]),
                          "r"(afr[mi][2]), "r"(afr[mi][3]),
                          "r"(bfr[ni][0]), "r"(bfr[ni][1]));
                }
        }

        if (kt + STAGES - 1 < KSTEPS) load_stage(kt + STAGES - 1);
        CP_COMMIT();
    }

    #pragma unroll
    for (int mi = 0; mi < 4; mi++) {
        const int row = m0 + wm + mi * 16 + g8;
        #pragma unroll
        for (int ni = 0; ni < 4; ni++) {
            const int col = n0 + wn + ni * 8 + tig * 2;
            const float b0 = bias[col], b1 = bias[col + 1];
            float2 v0 = make_float2(c[mi][ni][0] + b0, c[mi][ni][1] + b1);
            float2 v1 = make_float2(c[mi][ni][2] + b0, c[mi][ni][3] + b1);
            *reinterpret_cast<float2*>(&C[(size_t)row * Nn + col])       = v0;
            *reinterpret_cast<float2*>(&C[(size_t)(row + 8) * Nn + col]) = v1;
        }
    }
}

// ---------------- sampling (two-phase) + fused split of its output -----------
__global__ __launch_bounds__(256)
void sample_kernel(const float* __restrict__ refp)
{
    const int nq0 = blockIdx.x * QPB;
    const int tid = threadIdx.x;

    __shared__ float4 s_w[QPB * 128];
    __shared__ int4   s_t[QPB * 128];

    #pragma unroll
    for (int rep = 0; rep < 2; rep++) {
        const int task = tid + rep * 256;
        const int q    = task >> 7;
        const int rest = task & 127;
        const int l    = (rest & 15) >> 2;
        const int nq   = nq0 + q;

        float logit = g_attn[(size_t)nq * 128 + rest];
        float mx = logit;
        #pragma unroll
        for (int m = 8; m; m >>= 1)
            mx = fmaxf(mx, __shfl_xor_sync(0xffffffffu, mx, m, 16));
        float e = __expf(logit - mx);
        float ssum = e;
        #pragma unroll
        for (int m = 8; m; m >>= 1)
            ssum += __shfl_xor_sync(0xffffffffu, ssum, m, 16);
        const float aw = e * (1.0f / ssum);

        const int W  = 64 >> l;
        const int S0 = (16384 - (16384 >> (2 * l))) / 3;

        const float2 off = *reinterpret_cast<const float2*>(
            &g_off[(size_t)nq * CCH + rest * 2]);
        const float2 rp  = *reinterpret_cast<const float2*>(
            &refp[((size_t)nq * NL + l) * 2]);

        const float locx = fminf(fmaxf(rp.x + off.x, 0.0f), 1.0f);
        const float locy = fminf(fmaxf(rp.y + off.y, 0.0f), 1.0f);
        const float x = locx * (float)W - 0.5f;
        const float y = locy * (float)W - 0.5f;
        const int xf = (int)floorf(x);
        const int yf = (int)floorf(y);
        const int x0i = min(max(xf,     0), W - 1);
        const int x1i = min(max(xf + 1, 0), W - 1);
        const int y0i = min(max(yf,     0), W - 1);
        const int y1i = min(max(yf + 1, 0), W - 1);
        const float wx1 = (float)x1i - x;
        const float wx0 = x - (float)x0i;
        const float wy1 = (float)y1i - y;
        const float wy0 = y - (float)y0i;

        s_w[task] = make_float4(wx1 * wy1 * aw, wx1 * wy0 * aw,
                                wx0 * wy1 * aw, wx0 * wy0 * aw);
        s_t[task] = make_int4(S0 + y0i * W + x0i,
                              S0 + y1i * W + x0i,
                              S0 + y0i * W + x1i,
                              S0 + y1i * W + x1i);
    }
    __syncthreads();

    const int q  = tid >> 6;
    const int r  = tid & 63;
    const int h  = r >> 3;
    const int d4 = r & 7;
    const int nq = nq0 + q;
    const int n  = nq / LQ;

    const float4* vbase = reinterpret_cast<const float4*>(
        g_value + (size_t)n * LEN_IN * CCH + h * DH + d4 * 4);

    float4 acc = make_float4(0.0f, 0.0f, 0.0f, 0.0f);
    const int tb0 = q * 128 + h * 16;

    #pragma unroll
    for (int i = 0; i < 16; i++) {
        const float4 w  = s_w[tb0 + i];
        const int4   tt = s_t[tb0 + i];
        const float4 va = vbase[(size_t)tt.x * (CCH / 4)];
        const float4 vb = vbase[(size_t)tt.y * (CCH / 4)];
        const float4 vc = vbase[(size_t)tt.z * (CCH / 4)];
        const float4 vd = vbase[(size_t)tt.w * (CCH / 4)];
        acc.x += w.x * va.x + w.y * vb.x + w.z * vc.x + w.w * vd.x;
        acc.y += w.x * va.y + w.y * vb.y + w.z * vc.y + w.w * vd.y;
        acc.z += w.x * va.z + w.y * vb.z + w.z * vc.z + w.w * vd.z;
        acc.w += w.x * va.w + w.y * vb.w + w.z * vc.w + w.w * vd.w;
    }

    // fused split (t0,t1 only — x3 out-GEMM never reads the t2 segment)
    __align__(8) __nv_bfloat16 t0[4], t1[4];
    const float v4[4] = {acc.x, acc.y, acc.z, acc.w};
    #pragma unroll
    for (int j = 0; j < 4; j++) {
        t0[j] = __float2bfloat16(v4[j]);
        t1[j] = __float2bfloat16(v4[j] - __bfloat162float(t0[j]));
    }

    __nv_bfloat16* row = g_As + (size_t)nq * K3 + h * DH + d4 * 4;
    *reinterpret_cast<ushort4*>(row)       = *reinterpret_cast<ushort4*>(t0);
    *reinterpret_cast<ushort4*>(row + CCH) = *reinterpret_cast<ushort4*>(t1);
}

// ---------------- launch ------------------------------------------------------
extern "C" void kernel_launch(void* const* d_in, const int* in_sizes, int n_in,
                              void* d_out, int out_size)
{
    const float* query  = (const float*)d_in[0];
    const float* refp   = (const float*)d_in[1];
    const float* inputf = (const float*)d_in[2];
    const float* w_off  = (const float*)d_in[5];
    const float* b_off  = (const float*)d_in[6];
    const float* w_attn = (const float*)d_in[7];
    const float* b_attn = (const float*)d_in[8];
    const float* w_val  = (const float*)d_in[9];
    const float* b_val  = (const float*)d_in[10];
    const float* w_out  = (const float*)d_in[11];
    const float* b_out  = (const float*)d_in[12];
    float* out = (float*)d_out;

    cudaFuncSetAttribute(gemm_bf16x3,
                         cudaFuncAttributeMaxDynamicSharedMemorySize, GSMEM);

    float *gv, *go, *ga;
    cudaGetSymbolAddress((void**)&gv, g_value);
    cudaGetSymbolAddress((void**)&go, g_off);
    cudaGetSymbolAddress((void**)&ga, g_attn);
    __nv_bfloat16 *ain, *as, *btv, *btw;
    cudaGetSymbolAddress((void**)&ain, g_Ain);
    cudaGetSymbolAddress((void**)&as,  g_As);
    cudaGetSymbolAddress((void**)&btv, g_Btv);
    cudaGetSymbolAddress((void**)&btw, g_Btw);

    const dim3 blk(256);
    const dim3 gSplitA(MROWS);
    const dim3 gGemm256(2, MROWS / 128);
    const dim3 gGemm128(1, MROWS / 128);

    // splits for the TC GEMMs (value, out)
    split_weights<<<512, blk>>>(w_val, w_out);
    splitA_kernel<<<gSplitA, blk>>>(inputf, ain);

    // value = input_flatten @ w_val + b_val       (TC bf16x3 — bounded ~5e-6)
    gemm_bf16x3<<<gGemm256, blk, GSMEM>>>(CCH, ain, btv, b_val, gv);
    // off = query @ w_off + b_off                 (fp32 SIMT — exact path)
    sgemm_bias<<<gGemm256, blk>>>(MROWS, CCH, CCH, query, w_off, b_off, go);
    // attn logits = query @ w_attn + b_attn       (fp32 SIMT — exact path)
    sgemm_bias<<<gGemm128, blk>>>(MROWS, 128, CCH, query, w_attn, b_attn, ga);
    // sampling + fused split of sampled output
    sample_kernel<<<MROWS / QPB, blk>>>(refp);
    // out = samp @ w_out + b_out                  (TC bf16x3)
    gemm_bf16x3<<<gGemm256, blk, GSMEM>>>(CCH, as, btw, b_out, out);
}

// round 11
// speedup vs baseline: 1.4972x; 1.0848x over previous
#include <cuda_runtime.h>
#include <cuda_bf16.h>
#include <math.h>
#include <stdint.h>

// ---------------- problem constants ----------------
#define NB    4
#define LQ    5440
#define CCH   256
#define NH    8
#define NL    4
#define NP    4
#define DH    32
#define LEN_IN 5440
#define MROWS (NB * LQ)     // 21760
#define QPB   4
#define K3    (3 * CCH)     // 768 physical split storage [t0|t1|t2]
#define KLOG3 (3 * CCH)

// ---------------- scratch ----------------
__device__ float g_value[(size_t)MROWS * CCH];
__device__ float g_off  [(size_t)MROWS * CCH];
__device__ float g_attn [(size_t)MROWS * 128];

__device__ __nv_bfloat16 g_Ain[(size_t)MROWS * K3];   // split3(input_flatten)
__device__ __nv_bfloat16 g_As [(size_t)MROWS * K3];   // split(sampled), t0|t1 used
__device__ __nv_bfloat16 g_Btv[(size_t)CCH * K3];
__device__ __nv_bfloat16 g_Btw[(size_t)CCH * K3];

// x3 product schedule: t0s0 + t0s1 + t1s0
__device__ __constant__ int c_amap[3] = {0, 0, 1};
__device__ __constant__ int c_bmap[3] = {0, 1, 0};

// ---------------- fp32 -> bf16 splits ----------------
__device__ __forceinline__ void bf16_split3(float x, __nv_bfloat16& t0,
                                            __nv_bfloat16& t1, __nv_bfloat16& t2)
{
    t0 = __float2bfloat16(x);
    const float r1 = x - __bfloat162float(t0);
    t1 = __float2bfloat16(r1);
    t2 = __float2bfloat16(r1 - __bfloat162float(t1));
}

__global__ __launch_bounds__(256)
void splitA_kernel(const float* __restrict__ X, __nv_bfloat16* __restrict__ A3)
{
    const int idx = blockIdx.x * 256 + threadIdx.x;
    const int m = idx >> 8;
    const int k = idx & 255;
    __nv_bfloat16 t0, t1, t2;
    bf16_split3(X[idx], t0, t1, t2);
    __nv_bfloat16* row = A3 + (size_t)m * K3;
    row[k] = t0; row[CCH + k] = t1; row[2 * CCH + k] = t2;
}

__device__ __forceinline__ void splitB_body(const float* W, __nv_bfloat16* B3t,
                                            int Nn, int e)
{
    const int k = e / Nn;
    const int n = e - k * Nn;
    __nv_bfloat16 s0, s1, s2;
    bf16_split3(W[e], s0, s1, s2);
    __nv_bfloat16* row = B3t + (size_t)n * K3;
    row[k] = s0; row[CCH + k] = s1; row[2 * CCH + k] = s2;
}

__global__ __launch_bounds__(256)
void split_weights(const float* __restrict__ wv, const float* __restrict__ ww)
{
    const int b = blockIdx.x;
    const int t = threadIdx.x;
    if (b < 256) splitB_body(wv, g_Btv, CCH, b * 256 + t);
    else         splitB_body(ww, g_Btw, CCH, (b - 256) * 256 + t);
}

// ---------------- fused fp32 SIMT GEMM: [off | attn] ---------------------------
// A = query [M][256]. col-tiles 0,1 -> w_off/g_off (N=256); tile 2 -> w_attn/g_attn.
// BK=16, double-buffered smem, register-staged prefetch, 1 sync per k-chunk.
#define BM  128
#define BN  128
#define BK2 16
#define TM  8
#define TN  8
#define KQ  256

__global__ __launch_bounds__(256)
void sgemm_fused_oa(const float* __restrict__ A,
                    const float* __restrict__ Boff,
                    const float* __restrict__ Batt,
                    const float* __restrict__ bias_off,
                    const float* __restrict__ bias_att,
                    float* __restrict__ Coff,
                    float* __restrict__ Catt)
{
    __shared__ float As[2][BK2 * BM];   // transposed: As[k][m]
    __shared__ float Bs[2][BK2 * BN];   // row-major:  Bs[k][n]

    const int crow = blockIdx.y;
    const int ccol = blockIdx.x;        // 0,1 -> off ; 2 -> attn

    const float* B;  const float* bias;  float* C;  int NnB, NnC, colOff;
    if (ccol < 2) { B = Boff; bias = bias_off; C = Coff; NnB = 256; NnC = 256; colOff = ccol * BN; }
    else          { B = Batt; bias = bias_att; C = Catt; NnB = 128; NnC = 128; colOff = 0; }

    const int tid = threadIdx.x;
    const int threadRow = tid / (BN / TN);   // 0..15
    const int threadCol = tid % (BN / TN);   // 0..15

    // loader mapping
    const int rowA  = tid >> 2;              // 0..63 (also +64)
    const int colA4 = (tid & 3) * 4;         // 0,4,8,12
    const int rowB  = tid >> 5;              // 0..7 (also +8)
    const int colB4 = (tid & 31) * 4;        // 0..124

    const float* gA0 = A + (size_t)(crow * BM + rowA)      * KQ + colA4;
    const float* gA1 = A + (size_t)(crow * BM + rowA + 64) * KQ + colA4;
    const float* gB0 = B + (size_t)rowB       * NnB + colOff + colB4;
    const float* gB1 = B + (size_t)(rowB + 8) * NnB + colOff + colB4;

    float acc[TM * TN] = {0.0f};
    float regM[TM], regN[TN];

    // prologue: tile 0 -> smem[0]
    float4 a0 = *reinterpret_cast<const float4*>(gA0);
    float4 a1 = *reinterpret_cast<const float4*>(gA1);
    float4 b0 = *reinterpret_cast<const float4*>(gB0);
    float4 b1 = *reinterpret_cast<const float4*>(gB1);
    {
        const float av0[4] = {a0.x, a0.y, a0.z, a0.w};
        const float av1[4] = {a1.x, a1.y, a1.z, a1.w};
        #pragma unroll
        for (int j = 0; j < 4; j++) {
            As[0][(colA4 + j) * BM + rowA]      = av0[j];
            As[0][(colA4 + j) * BM + rowA + 64] = av1[j];
        }
        *reinterpret_cast<float4*>(&Bs[0][rowB * BN + colB4])       = b0;
        *reinterpret_cast<float4*>(&Bs[0][(rowB + 8) * BN + colB4]) = b1;
    }
    __syncthreads();

    #pragma unroll
    for (int it = 0; it < KQ / BK2; it++) {
        const int buf = it & 1;
        const bool more = (it + 1) < (KQ / BK2);
        if (more) {
            const int k0 = (it + 1) * BK2;
            a0 = *reinterpret_cast<const float4*>(gA0 + k0);
            a1 = *reinterpret_cast<const float4*>(gA1 + k0);
            b0 = *reinterpret_cast<const float4*>(gB0 + (size_t)k0 * NnB);
            b1 = *reinterpret_cast<const float4*>(gB1 + (size_t)k0 * NnB);
        }

        #pragma unroll
        for (int k = 0; k < BK2; k++) {
            #pragma unroll
            for (int i = 0; i < TM; i++)
                regM[i] = As[buf][k * BM + threadRow * TM + i];
            #pragma unroll
            for (int j = 0; j < TN; j++)
                regN[j] = Bs[buf][k * BN + threadCol * TN + j];
            #pragma unroll
            for (int i = 0; i < TM; i++)
                #pragma unroll
                for (int j = 0; j < TN; j++)
                    acc[i * TN + j] += regM[i] * regN[j];
        }

        if (more) {
            const float av0[4] = {a0.x, a0.y, a0.z, a0.w};
            const float av1[4] = {a1.x, a1.y, a1.z, a1.w};
            #pragma unroll
            for (int j = 0; j < 4; j++) {
                As[buf ^ 1][(colA4 + j) * BM + rowA]      = av0[j];
                As[buf ^ 1][(colA4 + j) * BM + rowA + 64] = av1[j];
            }
            *reinterpret_cast<float4*>(&Bs[buf ^ 1][rowB * BN + colB4])       = b0;
            *reinterpret_cast<float4*>(&Bs[buf ^ 1][(rowB + 8) * BN + colB4]) = b1;
        }
        __syncthreads();
    }

    float bj[TN];
    #pragma unroll
    for (int j = 0; j < TN; j++)
        bj[j] = bias[colOff + threadCol * TN + j];

    #pragma unroll
    for (int i = 0; i < TM; i++) {
        const int row = crow * BM + threadRow * TM + i;
        #pragma unroll
        for (int j = 0; j < TN; j += 4) {
            const int col = colOff + threadCol * TN + j;
            float4 o;
            o.x = acc[i * TN + j + 0] + bj[j + 0];
            o.y = acc[i * TN + j + 1] + bj[j + 1];
            o.z = acc[i * TN + j + 2] + bj[j + 2];
            o.w = acc[i * TN + j + 3] + bj[j + 3];
            *reinterpret_cast<float4*>(&C[(size_t)row * NnC + col]) = o;
        }
    }
}

// ---------------- bf16x3 tensor-core GEMM, cp.async 4-stage -------------------
#define GBK    32
#define GP     40
#define STAGES 4
#define OPELTS (128 * GP)
#define KSTEPS (KLOG3 / GBK)               // 24
#define GSMEM  (STAGES * 2 * OPELTS * 2)   // 81920 bytes

#define CP16(sm_, gp_) asm volatile( \
    "cp.async.cg.shared.global [%0], [%1], 16;" :: "r"(sm_), "l"(gp_))
#define CP_COMMIT()  asm volatile("cp.async.commit_group;")
#define CP_WAIT2()   asm volatile("cp.async.wait_group 2;")

__global__ __launch_bounds__(256)
void gemm_bf16x3(int Nn,
                 const __nv_bfloat16* __restrict__ A,
                 const __nv_bfloat16* __restrict__ Bt,
                 const float* __restrict__ bias,
                 float* __restrict__ C)
{
    extern __shared__ __nv_bfloat16 sm[];
    __nv_bfloat16* As_ = sm;
    __nv_bfloat16* Bs_ = sm + STAGES * OPELTS;

    const int m0 = blockIdx.y * 128;
    const int n0 = blockIdx.x * 128;
    const int tid  = threadIdx.x;
    const int wid  = tid >> 5;
    const int lane = tid & 31;
    const int wm = (wid >> 2) * 64;
    const int wn = (wid & 3) * 32;
    const int g8  = lane >> 2;
    const int tig = lane & 3;

    const int lrow = tid >> 2;
    const int lseg = tid & 3;
    const __nv_bfloat16* gA0 = A  + (size_t)(m0 + lrow)      * K3 + lseg * 8;
    const __nv_bfloat16* gA1 = A  + (size_t)(m0 + lrow + 64) * K3 + lseg * 8;
    const __nv_bfloat16* gB0 = Bt + (size_t)(n0 + lrow)      * K3 + lseg * 8;
    const __nv_bfloat16* gB1 = Bt + (size_t)(n0 + lrow + 64) * K3 + lseg * 8;
    const uint32_t sA0 = (uint32_t)__cvta_generic_to_shared(
        &As_[lrow * GP + lseg * 8]);
    const uint32_t sB0 = (uint32_t)__cvta_generic_to_shared(
        &Bs_[lrow * GP + lseg * 8]);

    float c[4][4][4];
    #pragma unroll
    for (int mi = 0; mi < 4; mi++)
        #pragma unroll
        for (int ni = 0; ni < 4; ni++)
            #pragma unroll
            for (int r = 0; r < 4; r++) c[mi][ni][r] = 0.0f;

    auto load_stage = [&](int st) {
        const int slot = st & (STAGES - 1);
        const int k0   = st * GBK;
        const int seg  = k0 >> 8;
        const int ka   = c_amap[seg] * CCH + (k0 & 255);
        const int kb   = c_bmap[seg] * CCH + (k0 & 255);
        const uint32_t so = slot * OPELTS * 2;
        CP16(sA0 + so,               gA0 + ka);
        CP16(sA0 + so + 64 * GP * 2, gA1 + ka);
        CP16(sB0 + so,               gB0 + kb);
        CP16(sB0 + so + 64 * GP * 2, gB1 + kb);
    };

    load_stage(0); CP_COMMIT();
    load_stage(1); CP_COMMIT();
    load_stage(2); CP_COMMIT();

    for (int kt = 0; kt < KSTEPS; kt++) {
        CP_WAIT2();
        __syncthreads();
        const __nv_bfloat16* Asl = As_ + (kt & (STAGES - 1)) * OPELTS;
        const __nv_bfloat16* Bsl = Bs_ + (kt & (STAGES - 1)) * OPELTS;

        #pragma unroll
        for (int h = 0; h < 2; h++) {
            uint32_t afr[4][4], bfr[4][2];
            #pragma unroll
            for (int mi = 0; mi < 4; mi++) {
                const int rb = (wm + mi * 16 + g8) * GP + h * 16 + tig * 2;
                afr[mi][0] = *reinterpret_cast<const uint32_t*>(&Asl[rb]);
                afr[mi][1] = *reinterpret_cast<const uint32_t*>(&Asl[rb + 8 * GP]);
                afr[mi][2] = *reinterpret_cast<const uint32_t*>(&Asl[rb + 8]);
                afr[mi][3] = *reinterpret_cast<const uint32_t*>(&Asl[rb + 8 * GP + 8]);
            }
            #pragma unroll
            for (int ni = 0; ni < 4; ni++) {
                const int rb = (wn + ni * 8 + g8) * GP + h * 16 + tig * 2;
                bfr[ni][0] = *reinterpret_cast<const uint32_t*>(&Bsl[rb]);
                bfr[ni][1] = *reinterpret_cast<const uint32_t*>(&Bsl[rb + 8]);
            }
            #pragma unroll
            for (int mi = 0; mi < 4; mi++)
                #pragma unroll
                for (int ni = 0; ni < 4; ni++) {
                    asm volatile(
                        "mma.sync.aligned.m16n8k16.row.col.f32.bf16.bf16.f32 "
                        "{%0,%1,%2,%3}, {%4,%5,%6,%7}, {%8,%9}, {%0,%1,%2,%3};"
                        : "+f"(c[mi][ni][0]), "+f"(c[mi][ni][1]),
                          "+f"(c[mi][ni][2]), "+f"(c[mi][ni][3])
                        : "r"(afr[mi][0]), "r"(afr[mi][1]),
                          "r"(afr[mi][2]), "r"(afr[mi][3]),
                          "r"(bfr[ni][0]), "r"(bfr[ni][1]));
                }
        }

        if (kt + STAGES - 1 < KSTEPS) load_stage(kt + STAGES - 1);
        CP_COMMIT();
    }

    #pragma unroll
    for (int mi = 0; mi < 4; mi++) {
        const int row = m0 + wm + mi * 16 + g8;
        #pragma unroll
        for (int ni = 0; ni < 4; ni++) {
            const int col = n0 + wn + ni * 8 + tig * 2;
            const float b0 = bias[col], b1 = bias[col + 1];
            float2 v0 = make_float2(c[mi][ni][0] + b0, c[mi][ni][1] + b1);
            float2 v1 = make_float2(c[mi][ni][2] + b0, c[mi][ni][3] + b1);
            *reinterpret_cast<float2*>(&C[(size_t)row * Nn + col])       = v0;
            *reinterpret_cast<float2*>(&C[(size_t)(row + 8) * Nn + col]) = v1;
        }
    }
}

// ---------------- sampling (two-phase) + fused split of its output -----------
__global__ __launch_bounds__(256)
void sample_kernel(const float* __restrict__ refp)
{
    const int nq0 = blockIdx.x * QPB;
    const int tid = threadIdx.x;

    __shared__ float4 s_w[QPB * 128];
    __shared__ int4   s_t[QPB * 128];

    #pragma unroll
    for (int rep = 0; rep < 2; rep++) {
        const int task = tid + rep * 256;
        const int q    = task >> 7;
        const int rest = task & 127;
        const int l    = (rest & 15) >> 2;
        const int nq   = nq0 + q;

        float logit = g_attn[(size_t)nq * 128 + rest];
        float mx = logit;
        #pragma unroll
        for (int m = 8; m; m >>= 1)
            mx = fmaxf(mx, __shfl_xor_sync(0xffffffffu, mx, m, 16));
        float e = __expf(logit - mx);
        float ssum = e;
        #pragma unroll
        for (int m = 8; m; m >>= 1)
            ssum += __shfl_xor_sync(0xffffffffu, ssum, m, 16);
        const float aw = e * (1.0f / ssum);

        const int W  = 64 >> l;
        const int S0 = (16384 - (16384 >> (2 * l))) / 3;

        const float2 off = *reinterpret_cast<const float2*>(
            &g_off[(size_t)nq * CCH + rest * 2]);
        const float2 rp  = *reinterpret_cast<const float2*>(
            &refp[((size_t)nq * NL + l) * 2]);

        const float locx = fminf(fmaxf(rp.x + off.x, 0.0f), 1.0f);
        const float locy = fminf(fmaxf(rp.y + off.y, 0.0f), 1.0f);
        const float x = locx * (float)W - 0.5f;
        const float y = locy * (float)W - 0.5f;
        const int xf = (int)floorf(x);
        const int yf = (int)floorf(y);
        const int x0i = min(max(xf,     0), W - 1);
        const int x1i = min(max(xf + 1, 0), W - 1);
        const int y0i = min(max(yf,     0), W - 1);
        const int y1i = min(max(yf + 1, 0), W - 1);
        const float wx1 = (float)x1i - x;
        const float wx0 = x - (float)x0i;
        const float wy1 = (float)y1i - y;
        const float wy0 = y - (float)y0i;

        s_w[task] = make_float4(wx1 * wy1 * aw, wx1 * wy0 * aw,
                                wx0 * wy1 * aw, wx0 * wy0 * aw);
        s_t[task] = make_int4(S0 + y0i * W + x0i,
                              S0 + y1i * W + x0i,
                              S0 + y0i * W + x1i,
                              S0 + y1i * W + x1i);
    }
    __syncthreads();

    const int q  = tid >> 6;
    const int r  = tid & 63;
    const int h  = r >> 3;
    const int d4 = r & 7;
    const int nq = nq0 + q;
    const int n  = nq / LQ;

    const float4* vbase = reinterpret_cast<const float4*>(
        g_value + (size_t)n * LEN_IN * CCH + h * DH + d4 * 4);

    float4 acc = make_float4(0.0f, 0.0f, 0.0f, 0.0f);
    const int tb0 = q * 128 + h * 16;

    #pragma unroll
    for (int i = 0; i < 16; i++) {
        const float4 w  = s_w[tb0 + i];
        const int4   tt = s_t[tb0 + i];
        const float4 va = vbase[(size_t)tt.x * (CCH / 4)];
        const float4 vb = vbase[(size_t)tt.y * (CCH / 4)];
        const float4 vc = vbase[(size_t)tt.z * (CCH / 4)];
        const float4 vd = vbase[(size_t)tt.w * (CCH / 4)];
        acc.x += w.x * va.x + w.y * vb.x + w.z * vc.x + w.w * vd.x;
        acc.y += w.x * va.y + w.y * vb.y + w.z * vc.y + w.w * vd.y;
        acc.z += w.x * va.z + w.y * vb.z + w.z * vc.z + w.w * vd.z;
        acc.w += w.x * va.w + w.y * vb.w + w.z * vc.w + w.w * vd.w;
    }

    // fused split (t0,t1 only — x3 out-GEMM never reads the t2 segment)
    __align__(8) __nv_bfloat16 t0[4], t1[4];
    const float v4[4] = {acc.x, acc.y, acc.z, acc.w};
    #pragma unroll
    for (int j = 0; j < 4; j++) {
        t0[j] = __float2bfloat16(v4[j]);
        t1[j] = __float2bfloat16(v4[j] - __bfloat162float(t0[j]));
    }

    __nv_bfloat16* row = g_As + (size_t)nq * K3 + h * DH + d4 * 4;
    *reinterpret_cast<ushort4*>(row)       = *reinterpret_cast<ushort4*>(t0);
    *reinterpret_cast<ushort4*>(row + CCH) = *reinterpret_cast<ushort4*>(t1);
}

// ---------------- launch ------------------------------------------------------
extern "C" void kernel_launch(void* const* d_in, const int* in_sizes, int n_in,
                              void* d_out, int out_size)
{
    const float* query  = (const float*)d_in[0];
    const float* refp   = (const float*)d_in[1];
    const float* inputf = (const float*)d_in[2];
    const float* w_off  = (const float*)d_in[5];
    const float* b_off  = (const float*)d_in[6];
    const float* w_attn = (const float*)d_in[7];
    const float* b_attn = (const float*)d_in[8];
    const float* w_val  = (const float*)d_in[9];
    const float* b_val  = (const float*)d_in[10];
    const float* w_out  = (const float*)d_in[11];
    const float* b_out  = (const float*)d_in[12];
    float* out = (float*)d_out;

    cudaFuncSetAttribute(gemm_bf16x3,
                         cudaFuncAttributeMaxDynamicSharedMemorySize, GSMEM);

    float *gv, *go, *ga;
    cudaGetSymbolAddress((void**)&gv, g_value);
    cudaGetSymbolAddress((void**)&go, g_off);
    cudaGetSymbolAddress((void**)&ga, g_attn);
    __nv_bfloat16 *ain, *as, *btv, *btw;
    cudaGetSymbolAddress((void**)&ain, g_Ain);
    cudaGetSymbolAddress((void**)&as,  g_As);
    cudaGetSymbolAddress((void**)&btv, g_Btv);
    cudaGetSymbolAddress((void**)&btw, g_Btw);

    const dim3 blk(256);
    const dim3 gSplitA(MROWS);
    const dim3 gGemm256(2, MROWS / 128);
    const dim3 gFused(3, MROWS / 128);     // off (2 tiles) + attn (1 tile)

    // splits for the TC GEMMs (value, out)
    split_weights<<<512, blk>>>(w_val, w_out);
    splitA_kernel<<<gSplitA, blk>>>(inputf, ain);

    // value = input_flatten @ w_val + b_val       (TC bf16x3 — bounded ~5e-6)
    gemm_bf16x3<<<gGemm256, blk, GSMEM>>>(CCH, ain, btv, b_val, gv);
    // off + attn logits                           (fused fp32 SIMT — exact path)
    sgemm_fused_oa<<<gFused, blk>>>(query, w_off, w_attn, b_off, b_attn, go, ga);
    // sampling + fused split of sampled output
    sample_kernel<<<MROWS / QPB, blk>>>(refp);
    // out = samp @ w_out + b_out                  (TC bf16x3)
    gemm_bf16x3<<<gGemm256, blk, GSMEM>>>(CCH, as, btw, b_out, out);
}

// round 12
// speedup vs baseline: 1.5349x; 1.0252x over previous
#include <cuda_runtime.h>
#include <cuda_bf16.h>
#include <math.h>
#include <stdint.h>

// ---------------- problem constants ----------------
#define NB    4
#define LQ    5440
#define CCH   256
#define NH    8
#define NL    4
#define NP    4
#define DH    32
#define LEN_IN 5440
#define MROWS (NB * LQ)     // 21760
#define QPB   4
#define K3    (3 * CCH)     // 768 physical split storage [t0|t1|t2]
#define KLOG3 (3 * CCH)

// ---------------- scratch ----------------
__device__ float g_value[(size_t)MROWS * CCH];
__device__ float g_off  [(size_t)MROWS * CCH];
__device__ float g_attn [(size_t)MROWS * 128];

__device__ __nv_bfloat16 g_Ain[(size_t)MROWS * K3];   // split3(input_flatten)
__device__ __nv_bfloat16 g_As [(size_t)MROWS * K3];   // split(sampled), t0|t1 used
__device__ __nv_bfloat16 g_Btv[(size_t)CCH * K3];
__device__ __nv_bfloat16 g_Btw[(size_t)CCH * K3];

// x3 product schedule: t0s0 + t0s1 + t1s0
__device__ __constant__ int c_amap[3] = {0, 0, 1};
__device__ __constant__ int c_bmap[3] = {0, 1, 0};

// ---------------- fp32 -> bf16 splits ----------------
__device__ __forceinline__ void bf16_split3(float x, __nv_bfloat16& t0,
                                            __nv_bfloat16& t1, __nv_bfloat16& t2)
{
    t0 = __float2bfloat16(x);
    const float r1 = x - __bfloat162float(t0);
    t1 = __float2bfloat16(r1);
    t2 = __float2bfloat16(r1 - __bfloat162float(t1));
}

__global__ __launch_bounds__(256)
void splitA_kernel(const float* __restrict__ X, __nv_bfloat16* __restrict__ A3)
{
    const int idx = blockIdx.x * 256 + threadIdx.x;
    const int m = idx >> 8;
    const int k = idx & 255;
    __nv_bfloat16 t0, t1, t2;
    bf16_split3(X[idx], t0, t1, t2);
    __nv_bfloat16* row = A3 + (size_t)m * K3;
    row[k] = t0; row[CCH + k] = t1; row[2 * CCH + k] = t2;
}

__device__ __forceinline__ void splitB_body(const float* W, __nv_bfloat16* B3t,
                                            int Nn, int e)
{
    const int k = e / Nn;
    const int n = e - k * Nn;
    __nv_bfloat16 s0, s1, s2;
    bf16_split3(W[e], s0, s1, s2);
    __nv_bfloat16* row = B3t + (size_t)n * K3;
    row[k] = s0; row[CCH + k] = s1; row[2 * CCH + k] = s2;
}

__global__ __launch_bounds__(256)
void split_weights(const float* __restrict__ wv, const float* __restrict__ ww)
{
    const int b = blockIdx.x;
    const int t = threadIdx.x;
    if (b < 256) splitB_body(wv, g_Btv, CCH, b * 256 + t);
    else         splitB_body(ww, g_Btw, CCH, (b - 256) * 256 + t);
}

// ---------------- device body: fp32 SIMT GEMM [off | attn] -------------------
#define BM  128
#define BN  128
#define BK2 16
#define TM  8
#define TN  8
#define KQ  256

__device__ __forceinline__
void simt_oa_body(char* smemRaw, int crow, int ccol,
                  const float* __restrict__ A,
                  const float* __restrict__ Boff,
                  const float* __restrict__ Batt,
                  const float* __restrict__ bias_off,
                  const float* __restrict__ bias_att,
                  float* __restrict__ Coff,
                  float* __restrict__ Catt)
{
    float (*As)[BK2 * BM] = reinterpret_cast<float (*)[BK2 * BM]>(smemRaw);
    float (*Bs)[BK2 * BN] = reinterpret_cast<float (*)[BK2 * BN]>(
        smemRaw + 2 * BK2 * BM * sizeof(float));

    const float* B;  const float* bias;  float* C;  int NnB, NnC, colOff;
    if (ccol < 2) { B = Boff; bias = bias_off; C = Coff; NnB = 256; NnC = 256; colOff = ccol * BN; }
    else          { B = Batt; bias = bias_att; C = Catt; NnB = 128; NnC = 128; colOff = 0; }

    const int tid = threadIdx.x;
    const int threadRow = tid / (BN / TN);
    const int threadCol = tid % (BN / TN);

    const int rowA  = tid >> 2;
    const int colA4 = (tid & 3) * 4;
    const int rowB  = tid >> 5;
    const int colB4 = (tid & 31) * 4;

    const float* gA0 = A + (size_t)(crow * BM + rowA)      * KQ + colA4;
    const float* gA1 = A + (size_t)(crow * BM + rowA + 64) * KQ + colA4;
    const float* gB0 = B + (size_t)rowB       * NnB + colOff + colB4;
    const float* gB1 = B + (size_t)(rowB + 8) * NnB + colOff + colB4;

    float acc[TM * TN] = {0.0f};
    float regM[TM], regN[TN];

    float4 a0 = *reinterpret_cast<const float4*>(gA0);
    float4 a1 = *reinterpret_cast<const float4*>(gA1);
    float4 b0 = *reinterpret_cast<const float4*>(gB0);
    float4 b1 = *reinterpret_cast<const float4*>(gB1);
    {
        const float av0[4] = {a0.x, a0.y, a0.z, a0.w};
        const float av1[4] = {a1.x, a1.y, a1.z, a1.w};
        #pragma unroll
        for (int j = 0; j < 4; j++) {
            As[0][(colA4 + j) * BM + rowA]      = av0[j];
            As[0][(colA4 + j) * BM + rowA + 64] = av1[j];
        }
        *reinterpret_cast<float4*>(&Bs[0][rowB * BN + colB4])       = b0;
        *reinterpret_cast<float4*>(&Bs[0][(rowB + 8) * BN + colB4]) = b1;
    }
    __syncthreads();

    #pragma unroll
    for (int it = 0; it < KQ / BK2; it++) {
        const int buf = it & 1;
        const bool more = (it + 1) < (KQ / BK2);
        if (more) {
            const int k0 = (it + 1) * BK2;
            a0 = *reinterpret_cast<const float4*>(gA0 + k0);
            a1 = *reinterpret_cast<const float4*>(gA1 + k0);
            b0 = *reinterpret_cast<const float4*>(gB0 + (size_t)k0 * NnB);
            b1 = *reinterpret_cast<const float4*>(gB1 + (size_t)k0 * NnB);
        }

        #pragma unroll
        for (int k = 0; k < BK2; k++) {
            #pragma unroll
            for (int i = 0; i < TM; i++)
                regM[i] = As[buf][k * BM + threadRow * TM + i];
            #pragma unroll
            for (int j = 0; j < TN; j++)
                regN[j] = Bs[buf][k * BN + threadCol * TN + j];
            #pragma unroll
            for (int i = 0; i < TM; i++)
                #pragma unroll
                for (int j = 0; j < TN; j++)
                    acc[i * TN + j] += regM[i] * regN[j];
        }

        if (more) {
            const float av0[4] = {a0.x, a0.y, a0.z, a0.w};
            const float av1[4] = {a1.x, a1.y, a1.z, a1.w};
            #pragma unroll
            for (int j = 0; j < 4; j++) {
                As[buf ^ 1][(colA4 + j) * BM + rowA]      = av0[j];
                As[buf ^ 1][(colA4 + j) * BM + rowA + 64] = av1[j];
            }
            *reinterpret_cast<float4*>(&Bs[buf ^ 1][rowB * BN + colB4])       = b0;
            *reinterpret_cast<float4*>(&Bs[buf ^ 1][(rowB + 8) * BN + colB4]) = b1;
        }
        __syncthreads();
    }

    float bj[TN];
    #pragma unroll
    for (int j = 0; j < TN; j++)
        bj[j] = bias[colOff + threadCol * TN + j];

    #pragma unroll
    for (int i = 0; i < TM; i++) {
        const int row = crow * BM + threadRow * TM + i;
        #pragma unroll
        for (int j = 0; j < TN; j += 4) {
            const int col = colOff + threadCol * TN + j;
            float4 o;
            o.x = acc[i * TN + j + 0] + bj[j + 0];
            o.y = acc[i * TN + j + 1] + bj[j + 1];
            o.z = acc[i * TN + j + 2] + bj[j + 2];
            o.w = acc[i * TN + j + 3] + bj[j + 3];
            *reinterpret_cast<float4*>(&C[(size_t)row * NnC + col]) = o;
        }
    }
}

// ---------------- device body: bf16x3 TC GEMM, cp.async 4-stage ---------------
#define GBK    32
#define GP     40
#define STAGES 4
#define OPELTS (128 * GP)
#define KSTEPS (KLOG3 / GBK)               // 24
#define GSMEM  (STAGES * 2 * OPELTS * 2)   // 81920 bytes

#define CP16(sm_, gp_) asm volatile( \
    "cp.async.cg.shared.global [%0], [%1], 16;" :: "r"(sm_), "l"(gp_))
#define CP_COMMIT()  asm volatile("cp.async.commit_group;")
#define CP_WAIT2()   asm volatile("cp.async.wait_group 2;")

__device__ __forceinline__
void tc_gemm_body(char* smemRaw, int m0, int n0, int Nn,
                  const __nv_bfloat16* __restrict__ A,
                  const __nv_bfloat16* __restrict__ Bt,
                  const float* __restrict__ bias,
                  float* __restrict__ C)
{
    __nv_bfloat16* As_ = reinterpret_cast<__nv_bfloat16*>(smemRaw);
    __nv_bfloat16* Bs_ = As_ + STAGES * OPELTS;

    const int tid  = threadIdx.x;
    const int wid  = tid >> 5;
    const int lane = tid & 31;
    const int wm = (wid >> 2) * 64;
    const int wn = (wid & 3) * 32;
    const int g8  = lane >> 2;
    const int tig = lane & 3;

    const int lrow = tid >> 2;
    const int lseg = tid & 3;
    const __nv_bfloat16* gA0 = A  + (size_t)(m0 + lrow)      * K3 + lseg * 8;
    const __nv_bfloat16* gA1 = A  + (size_t)(m0 + lrow + 64) * K3 + lseg * 8;
    const __nv_bfloat16* gB0 = Bt + (size_t)(n0 + lrow)      * K3 + lseg * 8;
    const __nv_bfloat16* gB1 = Bt + (size_t)(n0 + lrow + 64) * K3 + lseg * 8;
    const uint32_t sA0 = (uint32_t)__cvta_generic_to_shared(
        &As_[lrow * GP + lseg * 8]);
    const uint32_t sB0 = (uint32_t)__cvta_generic_to_shared(
        &Bs_[lrow * GP + lseg * 8]);

    float c[4][4][4];
    #pragma unroll
    for (int mi = 0; mi < 4; mi++)
        #pragma unroll
        for (int ni = 0; ni < 4; ni++)
            #pragma unroll
            for (int r = 0; r < 4; r++) c[mi][ni][r] = 0.0f;

    auto load_stage = [&](int st) {
        const int slot = st & (STAGES - 1);
        const int k0   = st * GBK;
        const int seg  = k0 >> 8;
        const int ka   = c_amap[seg] * CCH + (k0 & 255);
        const int kb   = c_bmap[seg] * CCH + (k0 & 255);
        const uint32_t so = slot * OPELTS * 2;
        CP16(sA0 + so,               gA0 + ka);
        CP16(sA0 + so + 64 * GP * 2, gA1 + ka);
        CP16(sB0 + so,               gB0 + kb);
        CP16(sB0 + so + 64 * GP * 2, gB1 + kb);
    };

    load_stage(0); CP_COMMIT();
    load_stage(1); CP_COMMIT();
    load_stage(2); CP_COMMIT();

    for (int kt = 0; kt < KSTEPS; kt++) {
        CP_WAIT2();
        __syncthreads();
        const __nv_bfloat16* Asl = As_ + (kt & (STAGES - 1)) * OPELTS;
        const __nv_bfloat16* Bsl = Bs_ + (kt & (STAGES - 1)) * OPELTS;

        #pragma unroll
        for (int h = 0; h < 2; h++) {
            uint32_t afr[4][4], bfr[4][2];
            #pragma unroll
            for (int mi = 0; mi < 4; mi++) {
                const int rb = (wm + mi * 16 + g8) * GP + h * 16 + tig * 2;
                afr[mi][0] = *reinterpret_cast<const uint32_t*>(&Asl[rb]);
                afr[mi][1] = *reinterpret_cast<const uint32_t*>(&Asl[rb + 8 * GP]);
                afr[mi][2] = *reinterpret_cast<const uint32_t*>(&Asl[rb + 8]);
                afr[mi][3] = *reinterpret_cast<const uint32_t*>(&Asl[rb + 8 * GP + 8]);
            }
            #pragma unroll
            for (int ni = 0; ni < 4; ni++) {
                const int rb = (wn + ni * 8 + g8) * GP + h * 16 + tig * 2;
                bfr[ni][0] = *reinterpret_cast<const uint32_t*>(&Bsl[rb]);
                bfr[ni][1] = *reinterpret_cast<const uint32_t*>(&Bsl[rb + 8]);
            }
            #pragma unroll
            for (int mi = 0; mi < 4; mi++)
                #pragma unroll
                for (int ni = 0; ni < 4; ni++) {
                    asm volatile(
                        "mma.sync.aligned.m16n8k16.row.col.f32.bf16.bf16.f32 "
                        "{%0,%1,%2,%3}, {%4,%5,%6,%7}, {%8,%9}, {%0,%1,%2,%3};"
                        : "+f"(c[mi][ni][0]), "+f"(c[mi][ni][1]),
                          "+f"(c[mi][ni][2]), "+f"(c[mi][ni][3])
                        : "r"(afr[mi][0]), "r"(afr[mi][1]),
                          "r"(afr[mi][2]), "r"(afr[mi][3]),
                          "r"(bfr[ni][0]), "r"(bfr[ni][1]));
                }
        }

        if (kt + STAGES - 1 < KSTEPS) load_stage(kt + STAGES - 1);
        CP_COMMIT();
    }

    #pragma unroll
    for (int mi = 0; mi < 4; mi++) {
        const int row = m0 + wm + mi * 16 + g8;
        #pragma unroll
        for (int ni = 0; ni < 4; ni++) {
            const int col = n0 + wn + ni * 8 + tig * 2;
            const float b0 = bias[col], b1 = bias[col + 1];
            float2 v0 = make_float2(c[mi][ni][0] + b0, c[mi][ni][1] + b1);
            float2 v1 = make_float2(c[mi][ni][2] + b0, c[mi][ni][3] + b1);
            *reinterpret_cast<float2*>(&C[(size_t)row * Nn + col])       = v0;
            *reinterpret_cast<float2*>(&C[(size_t)(row + 8) * Nn + col]) = v1;
        }
    }
}

// ---------------- mega kernel: TC value tiles + SIMT off/attn tiles ----------
// 850 blocks. role = bid % 5: 0,1 -> TC value (340 tiles); 2,3,4 -> SIMT oa (510).
__global__ __launch_bounds__(256)
void mega_gemm(const __nv_bfloat16* __restrict__ Ain,
               const __nv_bfloat16* __restrict__ Btv,
               const float* __restrict__ b_val,
               float* __restrict__ Cval,
               const float* __restrict__ query,
               const float* __restrict__ Boff,
               const float* __restrict__ Batt,
               const float* __restrict__ bias_off,
               const float* __restrict__ bias_att,
               float* __restrict__ Coff,
               float* __restrict__ Catt)
{
    extern __shared__ char smemRaw[];
    const int bid  = blockIdx.x;
    const int role = bid % 5;
    const int grp  = bid / 5;          // 0..169
    if (role < 2) {
        const int idx = grp * 2 + role;        // 0..339
        tc_gemm_body(smemRaw, (idx >> 1) * 128, (idx & 1) * 128, CCH,
                     Ain, Btv, b_val, Cval);
    } else {
        const int idx = grp * 3 + (role - 2);  // 0..509
        simt_oa_body(smemRaw, idx / 3, idx % 3,
                     query, Boff, Batt, bias_off, bias_att, Coff, Catt);
    }
}

// ---------------- standalone TC GEMM (out projection) ------------------------
__global__ __launch_bounds__(256)
void gemm_bf16x3(int Nn,
                 const __nv_bfloat16* __restrict__ A,
                 const __nv_bfloat16* __restrict__ Bt,
                 const float* __restrict__ bias,
                 float* __restrict__ C)
{
    extern __shared__ char smemRaw[];
    tc_gemm_body(smemRaw, blockIdx.y * 128, blockIdx.x * 128, Nn, A, Bt, bias, C);
}

// ---------------- sampling (two-phase) + fused split of its output -----------
__global__ __launch_bounds__(256)
void sample_kernel(const float* __restrict__ refp)
{
    const int nq0 = blockIdx.x * QPB;
    const int tid = threadIdx.x;

    __shared__ float4 s_w[QPB * 128];
    __shared__ int4   s_t[QPB * 128];

    #pragma unroll
    for (int rep = 0; rep < 2; rep++) {
        const int task = tid + rep * 256;
        const int q    = task >> 7;
        const int rest = task & 127;
        const int l    = (rest & 15) >> 2;
        const int nq   = nq0 + q;

        float logit = g_attn[(size_t)nq * 128 + rest];
        float mx = logit;
        #pragma unroll
        for (int m = 8; m; m >>= 1)
            mx = fmaxf(mx, __shfl_xor_sync(0xffffffffu, mx, m, 16));
        float e = __expf(logit - mx);
        float ssum = e;
        #pragma unroll
        for (int m = 8; m; m >>= 1)
            ssum += __shfl_xor_sync(0xffffffffu, ssum, m, 16);
        const float aw = e * (1.0f / ssum);

        const int W  = 64 >> l;
        const int S0 = (16384 - (16384 >> (2 * l))) / 3;

        const float2 off = *reinterpret_cast<const float2*>(
            &g_off[(size_t)nq * CCH + rest * 2]);
        const float2 rp  = *reinterpret_cast<const float2*>(
            &refp[((size_t)nq * NL + l) * 2]);

        const float locx = fminf(fmaxf(rp.x + off.x, 0.0f), 1.0f);
        const float locy = fminf(fmaxf(rp.y + off.y, 0.0f), 1.0f);
        const float x = locx * (float)W - 0.5f;
        const float y = locy * (float)W - 0.5f;
        const int xf = (int)floorf(x);
        const int yf = (int)floorf(y);
        const int x0i = min(max(xf,     0), W - 1);
        const int x1i = min(max(xf + 1, 0), W - 1);
        const int y0i = min(max(yf,     0), W - 1);
        const int y1i = min(max(yf + 1, 0), W - 1);
        const float wx1 = (float)x1i - x;
        const float wx0 = x - (float)x0i;
        const float wy1 = (float)y1i - y;
        const float wy0 = y - (float)y0i;

        s_w[task] = make_float4(wx1 * wy1 * aw, wx1 * wy0 * aw,
                                wx0 * wy1 * aw, wx0 * wy0 * aw);
        s_t[task] = make_int4(S0 + y0i * W + x0i,
                              S0 + y1i * W + x0i,
                              S0 + y0i * W + x1i,
                              S0 + y1i * W + x1i);
    }
    __syncthreads();

    const int q  = tid >> 6;
    const int r  = tid & 63;
    const int h  = r >> 3;
    const int d4 = r & 7;
    const int nq = nq0 + q;
    const int n  = nq / LQ;

    const float4* vbase = reinterpret_cast<const float4*>(
        g_value + (size_t)n * LEN_IN * CCH + h * DH + d4 * 4);

    float4 acc = make_float4(0.0f, 0.0f, 0.0f, 0.0f);
    const int tb0 = q * 128 + h * 16;

    #pragma unroll
    for (int i = 0; i < 16; i++) {
        const float4 w  = s_w[tb0 + i];
        const int4   tt = s_t[tb0 + i];
        const float4 va = vbase[(size_t)tt.x * (CCH / 4)];
        const float4 vb = vbase[(size_t)tt.y * (CCH / 4)];
        const float4 vc = vbase[(size_t)tt.z * (CCH / 4)];
        const float4 vd = vbase[(size_t)tt.w * (CCH / 4)];
        acc.x += w.x * va.x + w.y * vb.x + w.z * vc.x + w.w * vd.x;
        acc.y += w.x * va.y + w.y * vb.y + w.z * vc.y + w.w * vd.y;
        acc.z += w.x * va.z + w.y * vb.z + w.z * vc.z + w.w * vd.z;
        acc.w += w.x * va.w + w.y * vb.w + w.z * vc.w + w.w * vd.w;
    }

    // fused split (t0,t1 only — x3 out-GEMM never reads the t2 segment)
    __align__(8) __nv_bfloat16 t0[4], t1[4];
    const float v4[4] = {acc.x, acc.y, acc.z, acc.w};
    #pragma unroll
    for (int j = 0; j < 4; j++) {
        t0[j] = __float2bfloat16(v4[j]);
        t1[j] = __float2bfloat16(v4[j] - __bfloat162float(t0[j]));
    }

    __nv_bfloat16* row = g_As + (size_t)nq * K3 + h * DH + d4 * 4;
    *reinterpret_cast<ushort4*>(row)       = *reinterpret_cast<ushort4*>(t0);
    *reinterpret_cast<ushort4*>(row + CCH) = *reinterpret_cast<ushort4*>(t1);
}

// ---------------- launch ------------------------------------------------------
extern "C" void kernel_launch(void* const* d_in, const int* in_sizes, int n_in,
                              void* d_out, int out_size)
{
    const float* query  = (const float*)d_in[0];
    const float* refp   = (const float*)d_in[1];
    const float* inputf = (const float*)d_in[2];
    const float* w_off  = (const float*)d_in[5];
    const float* b_off  = (const float*)d_in[6];
    const float* w_attn = (const float*)d_in[7];
    const float* b_attn = (const float*)d_in[8];
    const float* w_val  = (const float*)d_in[9];
    const float* b_val  = (const float*)d_in[10];
    const float* w_out  = (const float*)d_in[11];
    const float* b_out  = (const float*)d_in[12];
    float* out = (float*)d_out;

    cudaFuncSetAttribute(gemm_bf16x3,
                         cudaFuncAttributeMaxDynamicSharedMemorySize, GSMEM);
    cudaFuncSetAttribute(mega_gemm,
                         cudaFuncAttributeMaxDynamicSharedMemorySize, GSMEM);

    float *gv, *go, *ga;
    cudaGetSymbolAddress((void**)&gv, g_value);
    cudaGetSymbolAddress((void**)&go, g_off);
    cudaGetSymbolAddress((void**)&ga, g_attn);
    __nv_bfloat16 *ain, *as, *btv, *btw;
    cudaGetSymbolAddress((void**)&ain, g_Ain);
    cudaGetSymbolAddress((void**)&as,  g_As);
    cudaGetSymbolAddress((void**)&btv, g_Btv);
    cudaGetSymbolAddress((void**)&btw, g_Btw);

    const dim3 blk(256);
    const dim3 gSplitA(MROWS);
    const dim3 gGemm256(2, MROWS / 128);

    // splits for the TC GEMMs (value, out)
    split_weights<<<512, blk>>>(w_val, w_out);
    splitA_kernel<<<gSplitA, blk>>>(inputf, ain);

    // value (TC) + off/attn (SIMT) fused into one launch — pipe overlap
    mega_gemm<<<850, blk, GSMEM>>>(ain, btv, b_val, gv,
                                   query, w_off, w_attn, b_off, b_attn, go, ga);

    // sampling + fused split of sampled output
    sample_kernel<<<MROWS / QPB, blk>>>(refp);

    // out = samp @ w_out + b_out                  (TC bf16x3)
    gemm_bf16x3<<<gGemm256, blk, GSMEM>>>(CCH, as, btw, b_out, out);
}

// round 13
// speedup vs baseline: 1.6591x; 1.0809x over previous
#include <cuda_runtime.h>
#include <cuda_bf16.h>
#include <cuda_fp16.h>
#include <math.h>
#include <stdint.h>

// ---------------- problem constants ----------------
#define NB    4
#define LQ    5440
#define CCH   256
#define NH    8
#define NL    4
#define NP    4
#define DH    32
#define LEN_IN 5440
#define MROWS (NB * LQ)     // 21760
#define QPB   8             // queries per sample block
#define K3    (3 * CCH)     // 768 physical split storage [t0|t1|t2]
#define KLOG3 (3 * CCH)

// ---------------- scratch ----------------
__device__ __half g_valueh[(size_t)MROWS * CCH];   // projected value, fp16
__device__ float g_off  [(size_t)MROWS * CCH];
__device__ float g_attn [(size_t)MROWS * 128];

__device__ __nv_bfloat16 g_Ain[(size_t)MROWS * K3];   // split3(input_flatten)
__device__ __nv_bfloat16 g_As [(size_t)MROWS * K3];   // split(sampled), t0|t1 used
__device__ __nv_bfloat16 g_Btv[(size_t)CCH * K3];
__device__ __nv_bfloat16 g_Btw[(size_t)CCH * K3];

// x3 product schedule: t0s0 + t0s1 + t1s0
__device__ __constant__ int c_amap[3] = {0, 0, 1};
__device__ __constant__ int c_bmap[3] = {0, 1, 0};

// ---------------- fp32 -> bf16 splits ----------------
__device__ __forceinline__ void bf16_split3(float x, __nv_bfloat16& t0,
                                            __nv_bfloat16& t1, __nv_bfloat16& t2)
{
    t0 = __float2bfloat16(x);
    const float r1 = x - __bfloat162float(t0);
    t1 = __float2bfloat16(r1);
    t2 = __float2bfloat16(r1 - __bfloat162float(t1));
}

__global__ __launch_bounds__(256)
void splitA_kernel(const float* __restrict__ X, __nv_bfloat16* __restrict__ A3)
{
    const int idx = blockIdx.x * 256 + threadIdx.x;
    const int m = idx >> 8;
    const int k = idx & 255;
    __nv_bfloat16 t0, t1, t2;
    bf16_split3(X[idx], t0, t1, t2);
    __nv_bfloat16* row = A3 + (size_t)m * K3;
    row[k] = t0; row[CCH + k] = t1; row[2 * CCH + k] = t2;
}

__device__ __forceinline__ void splitB_body(const float* W, __nv_bfloat16* B3t,
                                            int Nn, int e)
{
    const int k = e / Nn;
    const int n = e - k * Nn;
    __nv_bfloat16 s0, s1, s2;
    bf16_split3(W[e], s0, s1, s2);
    __nv_bfloat16* row = B3t + (size_t)n * K3;
    row[k] = s0; row[CCH + k] = s1; row[2 * CCH + k] = s2;
}

__global__ __launch_bounds__(256)
void split_weights(const float* __restrict__ wv, const float* __restrict__ ww)
{
    const int b = blockIdx.x;
    const int t = threadIdx.x;
    if (b < 256) splitB_body(wv, g_Btv, CCH, b * 256 + t);
    else         splitB_body(ww, g_Btw, CCH, (b - 256) * 256 + t);
}

// ---------------- device body: fp32 SIMT GEMM [off | attn] -------------------
#define BM  128
#define BN  128
#define BK2 16
#define TM  8
#define TN  8
#define KQ  256

__device__ __forceinline__
void simt_oa_body(char* smemRaw, int crow, int ccol,
                  const float* __restrict__ A,
                  const float* __restrict__ Boff,
                  const float* __restrict__ Batt,
                  const float* __restrict__ bias_off,
                  const float* __restrict__ bias_att,
                  float* __restrict__ Coff,
                  float* __restrict__ Catt)
{
    float (*As)[BK2 * BM] = reinterpret_cast<float (*)[BK2 * BM]>(smemRaw);
    float (*Bs)[BK2 * BN] = reinterpret_cast<float (*)[BK2 * BN]>(
        smemRaw + 2 * BK2 * BM * sizeof(float));

    const float* B;  const float* bias;  float* C;  int NnB, NnC, colOff;
    if (ccol < 2) { B = Boff; bias = bias_off; C = Coff; NnB = 256; NnC = 256; colOff = ccol * BN; }
    else          { B = Batt; bias = bias_att; C = Catt; NnB = 128; NnC = 128; colOff = 0; }

    const int tid = threadIdx.x;
    const int threadRow = tid / (BN / TN);
    const int threadCol = tid % (BN / TN);

    const int rowA  = tid >> 2;
    const int colA4 = (tid & 3) * 4;
    const int rowB  = tid >> 5;
    const int colB4 = (tid & 31) * 4;

    const float* gA0 = A + (size_t)(crow * BM + rowA)      * KQ + colA4;
    const float* gA1 = A + (size_t)(crow * BM + rowA + 64) * KQ + colA4;
    const float* gB0 = B + (size_t)rowB       * NnB + colOff + colB4;
    const float* gB1 = B + (size_t)(rowB + 8) * NnB + colOff + colB4;

    float acc[TM * TN] = {0.0f};
    float regM[TM], regN[TN];

    float4 a0 = *reinterpret_cast<const float4*>(gA0);
    float4 a1 = *reinterpret_cast<const float4*>(gA1);
    float4 b0 = *reinterpret_cast<const float4*>(gB0);
    float4 b1 = *reinterpret_cast<const float4*>(gB1);
    {
        const float av0[4] = {a0.x, a0.y, a0.z, a0.w};
        const float av1[4] = {a1.x, a1.y, a1.z, a1.w};
        #pragma unroll
        for (int j = 0; j < 4; j++) {
            As[0][(colA4 + j) * BM + rowA]      = av0[j];
            As[0][(colA4 + j) * BM + rowA + 64] = av1[j];
        }
        *reinterpret_cast<float4*>(&Bs[0][rowB * BN + colB4])       = b0;
        *reinterpret_cast<float4*>(&Bs[0][(rowB + 8) * BN + colB4]) = b1;
    }
    __syncthreads();

    #pragma unroll
    for (int it = 0; it < KQ / BK2; it++) {
        const int buf = it & 1;
        const bool more = (it + 1) < (KQ / BK2);
        if (more) {
            const int k0 = (it + 1) * BK2;
            a0 = *reinterpret_cast<const float4*>(gA0 + k0);
            a1 = *reinterpret_cast<const float4*>(gA1 + k0);
            b0 = *reinterpret_cast<const float4*>(gB0 + (size_t)k0 * NnB);
            b1 = *reinterpret_cast<const float4*>(gB1 + (size_t)k0 * NnB);
        }

        #pragma unroll
        for (int k = 0; k < BK2; k++) {
            #pragma unroll
            for (int i = 0; i < TM; i++)
                regM[i] = As[buf][k * BM + threadRow * TM + i];
            #pragma unroll
            for (int j = 0; j < TN; j++)
                regN[j] = Bs[buf][k * BN + threadCol * TN + j];
            #pragma unroll
            for (int i = 0; i < TM; i++)
                #pragma unroll
                for (int j = 0; j < TN; j++)
                    acc[i * TN + j] += regM[i] * regN[j];
        }

        if (more) {
            const float av0[4] = {a0.x, a0.y, a0.z, a0.w};
            const float av1[4] = {a1.x, a1.y, a1.z, a1.w};
            #pragma unroll
            for (int j = 0; j < 4; j++) {
                As[buf ^ 1][(colA4 + j) * BM + rowA]      = av0[j];
                As[buf ^ 1][(colA4 + j) * BM + rowA + 64] = av1[j];
            }
            *reinterpret_cast<float4*>(&Bs[buf ^ 1][rowB * BN + colB4])       = b0;
            *reinterpret_cast<float4*>(&Bs[buf ^ 1][(rowB + 8) * BN + colB4]) = b1;
        }
        __syncthreads();
    }

    float bj[TN];
    #pragma unroll
    for (int j = 0; j < TN; j++)
        bj[j] = bias[colOff + threadCol * TN + j];

    #pragma unroll
    for (int i = 0; i < TM; i++) {
        const int row = crow * BM + threadRow * TM + i;
        #pragma unroll
        for (int j = 0; j < TN; j += 4) {
            const int col = colOff + threadCol * TN + j;
            float4 o;
            o.x = acc[i * TN + j + 0] + bj[j + 0];
            o.y = acc[i * TN + j + 1] + bj[j + 1];
            o.z = acc[i * TN + j + 2] + bj[j + 2];
            o.w = acc[i * TN + j + 3] + bj[j + 3];
            *reinterpret_cast<float4*>(&C[(size_t)row * NnC + col]) = o;
        }
    }
}

// ---------------- device body: bf16x3 TC GEMM, cp.async 4-stage ---------------
#define GBK    32
#define GP     40
#define STAGES 4
#define OPELTS (128 * GP)
#define KSTEPS (KLOG3 / GBK)               // 24
#define GSMEM  (STAGES * 2 * OPELTS * 2)   // 81920 bytes

#define CP16(sm_, gp_) asm volatile( \
    "cp.async.cg.shared.global [%0], [%1], 16;" :: "r"(sm_), "l"(gp_))
#define CP_COMMIT()  asm volatile("cp.async.commit_group;")
#define CP_WAIT2()   asm volatile("cp.async.wait_group 2;")

// If Chalf != nullptr, write fp16 output there; else write fp32 to C.
__device__ __forceinline__
void tc_gemm_body(char* smemRaw, int m0, int n0, int Nn,
                  const __nv_bfloat16* __restrict__ A,
                  const __nv_bfloat16* __restrict__ Bt,
                  const float* __restrict__ bias,
                  float* __restrict__ C,
                  __half* __restrict__ Chalf)
{
    __nv_bfloat16* As_ = reinterpret_cast<__nv_bfloat16*>(smemRaw);
    __nv_bfloat16* Bs_ = As_ + STAGES * OPELTS;

    const int tid  = threadIdx.x;
    const int wid  = tid >> 5;
    const int lane = tid & 31;
    const int wm = (wid >> 2) * 64;
    const int wn = (wid & 3) * 32;
    const int g8  = lane >> 2;
    const int tig = lane & 3;

    const int lrow = tid >> 2;
    const int lseg = tid & 3;
    const __nv_bfloat16* gA0 = A  + (size_t)(m0 + lrow)      * K3 + lseg * 8;
    const __nv_bfloat16* gA1 = A  + (size_t)(m0 + lrow + 64) * K3 + lseg * 8;
    const __nv_bfloat16* gB0 = Bt + (size_t)(n0 + lrow)      * K3 + lseg * 8;
    const __nv_bfloat16* gB1 = Bt + (size_t)(n0 + lrow + 64) * K3 + lseg * 8;
    const uint32_t sA0 = (uint32_t)__cvta_generic_to_shared(
        &As_[lrow * GP + lseg * 8]);
    const uint32_t sB0 = (uint32_t)__cvta_generic_to_shared(
        &Bs_[lrow * GP + lseg * 8]);

    float c[4][4][4];
    #pragma unroll
    for (int mi = 0; mi < 4; mi++)
        #pragma unroll
        for (int ni = 0; ni < 4; ni++)
            #pragma unroll
            for (int r = 0; r < 4; r++) c[mi][ni][r] = 0.0f;

    auto load_stage = [&](int st) {
        const int slot = st & (STAGES - 1);
        const int k0   = st * GBK;
        const int seg  = k0 >> 8;
        const int ka   = c_amap[seg] * CCH + (k0 & 255);
        const int kb   = c_bmap[seg] * CCH + (k0 & 255);
        const uint32_t so = slot * OPELTS * 2;
        CP16(sA0 + so,               gA0 + ka);
        CP16(sA0 + so + 64 * GP * 2, gA1 + ka);
        CP16(sB0 + so,               gB0 + kb);
        CP16(sB0 + so + 64 * GP * 2, gB1 + kb);
    };

    load_stage(0); CP_COMMIT();
    load_stage(1); CP_COMMIT();
    load_stage(2); CP_COMMIT();

    for (int kt = 0; kt < KSTEPS; kt++) {
        CP_WAIT2();
        __syncthreads();
        const __nv_bfloat16* Asl = As_ + (kt & (STAGES - 1)) * OPELTS;
        const __nv_bfloat16* Bsl = Bs_ + (kt & (STAGES - 1)) * OPELTS;

        #pragma unroll
        for (int h = 0; h < 2; h++) {
            uint32_t afr[4][4], bfr[4][2];
            #pragma unroll
            for (int mi = 0; mi < 4; mi++) {
                const int rb = (wm + mi * 16 + g8) * GP + h * 16 + tig * 2;
                afr[mi][0] = *reinterpret_cast<const uint32_t*>(&Asl[rb]);
                afr[mi][1] = *reinterpret_cast<const uint32_t*>(&Asl[rb + 8 * GP]);
                afr[mi][2] = *reinterpret_cast<const uint32_t*>(&Asl[rb + 8]);
                afr[mi][3] = *reinterpret_cast<const uint32_t*>(&Asl[rb + 8 * GP + 8]);
            }
            #pragma unroll
            for (int ni = 0; ni < 4; ni++) {
                const int rb = (wn + ni * 8 + g8) * GP + h * 16 + tig * 2;
                bfr[ni][0] = *reinterpret_cast<const uint32_t*>(&Bsl[rb]);
                bfr[ni][1] = *reinterpret_cast<const uint32_t*>(&Bsl[rb + 8]);
            }
            #pragma unroll
            for (int mi = 0; mi < 4; mi++)
                #pragma unroll
                for (int ni = 0; ni < 4; ni++) {
                    asm volatile(
                        "mma.sync.aligned.m16n8k16.row.col.f32.bf16.bf16.f32 "
                        "{%0,%1,%2,%3}, {%4,%5,%6,%7}, {%8,%9}, {%0,%1,%2,%3};"
                        : "+f"(c[mi][ni][0]), "+f"(c[mi][ni][1]),
                          "+f"(c[mi][ni][2]), "+f"(c[mi][ni][3])
                        : "r"(afr[mi][0]), "r"(afr[mi][1]),
                          "r"(afr[mi][2]), "r"(afr[mi][3]),
                          "r"(bfr[ni][0]), "r"(bfr[ni][1]));
                }
        }

        if (kt + STAGES - 1 < KSTEPS) load_stage(kt + STAGES - 1);
        CP_COMMIT();
    }

    #pragma unroll
    for (int mi = 0; mi < 4; mi++) {
        const int row = m0 + wm + mi * 16 + g8;
        #pragma unroll
        for (int ni = 0; ni < 4; ni++) {
            const int col = n0 + wn + ni * 8 + tig * 2;
            const float b0 = bias[col], b1 = bias[col + 1];
            const float v00 = c[mi][ni][0] + b0, v01 = c[mi][ni][1] + b1;
            const float v10 = c[mi][ni][2] + b0, v11 = c[mi][ni][3] + b1;
            if (Chalf) {
                *reinterpret_cast<__half2*>(&Chalf[(size_t)row * Nn + col]) =
                    __floats2half2_rn(v00, v01);
                *reinterpret_cast<__half2*>(&Chalf[(size_t)(row + 8) * Nn + col]) =
                    __floats2half2_rn(v10, v11);
            } else {
                *reinterpret_cast<float2*>(&C[(size_t)row * Nn + col]) =
                    make_float2(v00, v01);
                *reinterpret_cast<float2*>(&C[(size_t)(row + 8) * Nn + col]) =
                    make_float2(v10, v11);
            }
        }
    }
}

// ---------------- mega kernel: TC value tiles + SIMT off/attn tiles ----------
__global__ __launch_bounds__(256)
void mega_gemm(const __nv_bfloat16* __restrict__ Ain,
               const __nv_bfloat16* __restrict__ Btv,
               const float* __restrict__ b_val,
               const float* __restrict__ query,
               const float* __restrict__ Boff,
               const float* __restrict__ Batt,
               const float* __restrict__ bias_off,
               const float* __restrict__ bias_att,
               float* __restrict__ Coff,
               float* __restrict__ Catt)
{
    extern __shared__ char smemRaw[];
    const int bid  = blockIdx.x;
    const int role = bid % 5;
    const int grp  = bid / 5;          // 0..169
    if (role < 2) {
        const int idx = grp * 2 + role;        // 0..339
        tc_gemm_body(smemRaw, (idx >> 1) * 128, (idx & 1) * 128, CCH,
                     Ain, Btv, b_val, nullptr, g_valueh);
    } else {
        const int idx = grp * 3 + (role - 2);  // 0..509
        simt_oa_body(smemRaw, idx / 3, idx % 3,
                     query, Boff, Batt, bias_off, bias_att, Coff, Catt);
    }
}

// ---------------- standalone TC GEMM (out projection, fp32 out) --------------
__global__ __launch_bounds__(256)
void gemm_bf16x3(int Nn,
                 const __nv_bfloat16* __restrict__ A,
                 const __nv_bfloat16* __restrict__ Bt,
                 const float* __restrict__ bias,
                 float* __restrict__ C)
{
    extern __shared__ char smemRaw[];
    tc_gemm_body(smemRaw, blockIdx.y * 128, blockIdx.x * 128, Nn,
                 A, Bt, bias, C, nullptr);
}

// ---------------- sampling: fp16 gathers, 8 queries/block --------------------
__global__ __launch_bounds__(256)
void sample_kernel(const float* __restrict__ refp)
{
    const int nq0 = blockIdx.x * QPB;
    const int tid = threadIdx.x;

    __shared__ float4 s_w[QPB * 128];
    __shared__ int4   s_t[QPB * 128];

    // ---------- phase 1: per (q,h,point) weights + indices ----------
    #pragma unroll
    for (int rep = 0; rep < QPB * 128 / 256; rep++) {   // 4 reps
        const int task = tid + rep * 256;
        const int q    = task >> 7;
        const int rest = task & 127;
        const int l    = (rest & 15) >> 2;
        const int nq   = nq0 + q;

        float logit = g_attn[(size_t)nq * 128 + rest];
        float mx = logit;
        #pragma unroll
        for (int m = 8; m; m >>= 1)
            mx = fmaxf(mx, __shfl_xor_sync(0xffffffffu, mx, m, 16));
        float e = __expf(logit - mx);
        float ssum = e;
        #pragma unroll
        for (int m = 8; m; m >>= 1)
            ssum += __shfl_xor_sync(0xffffffffu, ssum, m, 16);
        const float aw = e * (1.0f / ssum);

        const int W  = 64 >> l;
        const int S0 = (16384 - (16384 >> (2 * l))) / 3;

        const float2 off = *reinterpret_cast<const float2*>(
            &g_off[(size_t)nq * CCH + rest * 2]);
        const float2 rp  = *reinterpret_cast<const float2*>(
            &refp[((size_t)nq * NL + l) * 2]);

        const float locx = fminf(fmaxf(rp.x + off.x, 0.0f), 1.0f);
        const float locy = fminf(fmaxf(rp.y + off.y, 0.0f), 1.0f);
        const float x = locx * (float)W - 0.5f;
        const float y = locy * (float)W - 0.5f;
        const int xf = (int)floorf(x);
        const int yf = (int)floorf(y);
        const int x0i = min(max(xf,     0), W - 1);
        const int x1i = min(max(xf + 1, 0), W - 1);
        const int y0i = min(max(yf,     0), W - 1);
        const int y1i = min(max(yf + 1, 0), W - 1);
        const float wx1 = (float)x1i - x;
        const float wx0 = x - (float)x0i;
        const float wy1 = (float)y1i - y;
        const float wy0 = y - (float)y0i;

        s_w[task] = make_float4(wx1 * wy1 * aw, wx1 * wy0 * aw,
                                wx0 * wy1 * aw, wx0 * wy0 * aw);
        s_t[task] = make_int4(S0 + y0i * W + x0i,
                              S0 + y1i * W + x0i,
                              S0 + y0i * W + x1i,
                              S0 + y1i * W + x1i);
    }
    __syncthreads();

    // ---------- phase 2: fp16 gathers, 4 threads per (q,h), 8 halves each ----
    const int q  = tid >> 5;        // 0..7
    const int r  = tid & 31;
    const int h  = r >> 2;          // 0..7
    const int d8 = r & 3;           // 0..3 (8-half group)
    const int nq = nq0 + q;
    const int n  = nq / LQ;

    const __half* vb = g_valueh + (size_t)n * LEN_IN * CCH + h * DH + d8 * 8;

    float acc[8];
    #pragma unroll
    for (int j = 0; j < 8; j++) acc[j] = 0.0f;
    const int tb0 = q * 128 + h * 16;

    #pragma unroll
    for (int i = 0; i < 16; i++) {
        const float4 w  = s_w[tb0 + i];
        const int4   tt = s_t[tb0 + i];
        const uint4 ua = *reinterpret_cast<const uint4*>(vb + (size_t)tt.x * CCH);
        const uint4 ub = *reinterpret_cast<const uint4*>(vb + (size_t)tt.y * CCH);
        const uint4 uc = *reinterpret_cast<const uint4*>(vb + (size_t)tt.z * CCH);
        const uint4 ud = *reinterpret_cast<const uint4*>(vb + (size_t)tt.w * CCH);
        const __half2* ha = reinterpret_cast<const __half2*>(&ua);
        const __half2* hb = reinterpret_cast<const __half2*>(&ub);
        const __half2* hc = reinterpret_cast<const __half2*>(&uc);
        const __half2* hd = reinterpret_cast<const __half2*>(&ud);
        #pragma unroll
        for (int p = 0; p < 4; p++) {
            const float2 fa = __half22float2(ha[p]);
            const float2 fb = __half22float2(hb[p]);
            const float2 fc = __half22float2(hc[p]);
            const float2 fd = __half22float2(hd[p]);
            acc[2*p]   += w.x * fa.x + w.y * fb.x + w.z * fc.x + w.w * fd.x;
            acc[2*p+1] += w.x * fa.y + w.y * fb.y + w.z * fc.y + w.w * fd.y;
        }
    }

    // fused split (t0,t1 only — x3 out-GEMM never reads the t2 segment)
    __align__(8) __nv_bfloat16 t0[8], t1[8];
    #pragma unroll
    for (int j = 0; j < 8; j++) {
        t0[j] = __float2bfloat16(acc[j]);
        t1[j] = __float2bfloat16(acc[j] - __bfloat162float(t0[j]));
    }

    __nv_bfloat16* row = g_As + (size_t)nq * K3 + h * DH + d8 * 8;
    *reinterpret_cast<ushort4*>(row)           = *reinterpret_cast<ushort4*>(t0);
    *reinterpret_cast<ushort4*>(row + 4)       = *reinterpret_cast<ushort4*>(t0 + 4);
    *reinterpret_cast<ushort4*>(row + CCH)     = *reinterpret_cast<ushort4*>(t1);
    *reinterpret_cast<ushort4*>(row + CCH + 4) = *reinterpret_cast<ushort4*>(t1 + 4);
}

// ---------------- launch ------------------------------------------------------
extern "C" void kernel_launch(void* const* d_in, const int* in_sizes, int n_in,
                              void* d_out, int out_size)
{
    const float* query  = (const float*)d_in[0];
    const float* refp   = (const float*)d_in[1];
    const float* inputf = (const float*)d_in[2];
    const float* w_off  = (const float*)d_in[5];
    const float* b_off  = (const float*)d_in[6];
    const float* w_attn = (const float*)d_in[7];
    const float* b_attn = (const float*)d_in[8];
    const float* w_val  = (const float*)d_in[9];
    const float* b_val  = (const float*)d_in[10];
    const float* w_out  = (const float*)d_in[11];
    const float* b_out  = (const float*)d_in[12];
    float* out = (float*)d_out;

    cudaFuncSetAttribute(gemm_bf16x3,
                         cudaFuncAttributeMaxDynamicSharedMemorySize, GSMEM);
    cudaFuncSetAttribute(mega_gemm,
                         cudaFuncAttributeMaxDynamicSharedMemorySize, GSMEM);

    float *go, *ga;
    cudaGetSymbolAddress((void**)&go, g_off);
    cudaGetSymbolAddress((void**)&ga, g_attn);
    __nv_bfloat16 *ain, *as, *btv, *btw;
    cudaGetSymbolAddress((void**)&ain, g_Ain);
    cudaGetSymbolAddress((void**)&as,  g_As);
    cudaGetSymbolAddress((void**)&btv, g_Btv);
    cudaGetSymbolAddress((void**)&btw, g_Btw);

    const dim3 blk(256);
    const dim3 gSplitA(MROWS);
    const dim3 gGemm256(2, MROWS / 128);

    // splits for the TC GEMMs (value, out)
    split_weights<<<512, blk>>>(w_val, w_out);
    splitA_kernel<<<gSplitA, blk>>>(inputf, ain);

    // value (TC -> fp16 out) + off/attn (SIMT fp32) fused — pipe overlap
    mega_gemm<<<850, blk, GSMEM>>>(ain, btv, b_val,
                                   query, w_off, w_attn, b_off, b_attn, go, ga);

    // sampling (fp16 gathers) + fused split of sampled output
    sample_kernel<<<MROWS / QPB, blk>>>(refp);

    // out = samp @ w_out + b_out                  (TC bf16x3, fp32 out)
    gemm_bf16x3<<<gGemm256, blk, GSMEM>>>(CCH, as, btw, b_out, out);
}

// round 14
// speedup vs baseline: 1.7504x; 1.0550x over previous
#include <cuda_runtime.h>
#include <cuda_bf16.h>
#include <cuda_fp16.h>
#include <math.h>
#include <stdint.h>

// ---------------- problem constants ----------------
#define NB    4
#define LQ    5440
#define CCH   256
#define NH    8
#define NL    4
#define NP    4
#define DH    32
#define LEN_IN 5440
#define MROWS (NB * LQ)     // 21760
#define QPB   8             // queries per sample block
#define K3    (3 * CCH)     // 768 physical split storage [t0|t1|t2]
#define KLOG3 (3 * CCH)

// ---------------- scratch ----------------
__device__ __half g_valueh[(size_t)MROWS * CCH];   // projected value, fp16
__device__ float g_off  [(size_t)MROWS * CCH];
__device__ float g_attn [(size_t)MROWS * 128];

__device__ __nv_bfloat16 g_Ain[(size_t)MROWS * K3];   // split3(input_flatten)
__device__ __nv_bfloat16 g_As [(size_t)MROWS * K3];   // split(sampled), t0|t1 used
__device__ __nv_bfloat16 g_Btv[(size_t)CCH * K3];
__device__ __nv_bfloat16 g_Btw[(size_t)CCH * K3];

// x3 product schedule: t0s0 + t0s1 + t1s0
__device__ __constant__ int c_amap[3] = {0, 0, 1};
__device__ __constant__ int c_bmap[3] = {0, 1, 0};

// ---------------- fp32 -> bf16 splits ----------------
__device__ __forceinline__ void bf16_split3(float x, __nv_bfloat16& t0,
                                            __nv_bfloat16& t1, __nv_bfloat16& t2)
{
    t0 = __float2bfloat16(x);
    const float r1 = x - __bfloat162float(t0);
    t1 = __float2bfloat16(r1);
    t2 = __float2bfloat16(r1 - __bfloat162float(t1));
}

__global__ __launch_bounds__(256)
void splitA_kernel(const float* __restrict__ X, __nv_bfloat16* __restrict__ A3)
{
    const int idx = blockIdx.x * 256 + threadIdx.x;
    const int m = idx >> 8;
    const int k = idx & 255;
    __nv_bfloat16 t0, t1, t2;
    bf16_split3(X[idx], t0, t1, t2);
    __nv_bfloat16* row = A3 + (size_t)m * K3;
    row[k] = t0; row[CCH + k] = t1; row[2 * CCH + k] = t2;
}

__device__ __forceinline__ void splitB_body(const float* W, __nv_bfloat16* B3t,
                                            int Nn, int e)
{
    const int k = e / Nn;
    const int n = e - k * Nn;
    __nv_bfloat16 s0, s1, s2;
    bf16_split3(W[e], s0, s1, s2);
    __nv_bfloat16* row = B3t + (size_t)n * K3;
    row[k] = s0; row[CCH + k] = s1; row[2 * CCH + k] = s2;
}

__global__ __launch_bounds__(256)
void split_weights(const float* __restrict__ wv, const float* __restrict__ ww)
{
    const int b = blockIdx.x;
    const int t = threadIdx.x;
    if (b < 256) splitB_body(wv, g_Btv, CCH, b * 256 + t);
    else         splitB_body(ww, g_Btw, CCH, (b - 256) * 256 + t);
}

// ---------------- packed dual-fp32 FMA (FFMA2 via PTX) ------------------------
__device__ __forceinline__ void fma2(uint64_t& d, uint64_t a, uint64_t b)
{
    asm("fma.rn.f32x2 %0, %1, %2, %0;" : "+l"(d) : "l"(a), "l"(b));
}

// ---------------- device body: fp32 SIMT GEMM [off | attn] -------------------
#define BM  128
#define BN  128
#define BK2 16
#define TM  8
#define TN  8
#define KQ  256

__device__ __forceinline__
void simt_oa_body(char* smemRaw, int crow, int ccol,
                  const float* __restrict__ A,
                  const float* __restrict__ Boff,
                  const float* __restrict__ Batt,
                  const float* __restrict__ bias_off,
                  const float* __restrict__ bias_att,
                  float* __restrict__ Coff,
                  float* __restrict__ Catt)
{
    float (*As)[BK2 * BM] = reinterpret_cast<float (*)[BK2 * BM]>(smemRaw);
    float (*Bs)[BK2 * BN] = reinterpret_cast<float (*)[BK2 * BN]>(
        smemRaw + 2 * BK2 * BM * sizeof(float));

    const float* B;  const float* bias;  float* C;  int NnB, NnC, colOff;
    if (ccol < 2) { B = Boff; bias = bias_off; C = Coff; NnB = 256; NnC = 256; colOff = ccol * BN; }
    else          { B = Batt; bias = bias_att; C = Catt; NnB = 128; NnC = 128; colOff = 0; }

    const int tid = threadIdx.x;
    const int threadRow = tid / (BN / TN);
    const int threadCol = tid % (BN / TN);

    const int rowA  = tid >> 2;
    const int colA4 = (tid & 3) * 4;
    const int rowB  = tid >> 5;
    const int colB4 = (tid & 31) * 4;

    const float* gA0 = A + (size_t)(crow * BM + rowA)      * KQ + colA4;
    const float* gA1 = A + (size_t)(crow * BM + rowA + 64) * KQ + colA4;
    const float* gB0 = B + (size_t)rowB       * NnB + colOff + colB4;
    const float* gB1 = B + (size_t)(rowB + 8) * NnB + colOff + colB4;

    // packed accumulators: accp[i][j2] holds cols (j2*2, j2*2+1) of row i
    uint64_t accp[TM * (TN / 2)];
    #pragma unroll
    for (int i = 0; i < TM * (TN / 2); i++) accp[i] = 0ull;

    float4 a0 = *reinterpret_cast<const float4*>(gA0);
    float4 a1 = *reinterpret_cast<const float4*>(gA1);
    float4 b0 = *reinterpret_cast<const float4*>(gB0);
    float4 b1 = *reinterpret_cast<const float4*>(gB1);
    {
        const float av0[4] = {a0.x, a0.y, a0.z, a0.w};
        const float av1[4] = {a1.x, a1.y, a1.z, a1.w};
        #pragma unroll
        for (int j = 0; j < 4; j++) {
            As[0][(colA4 + j) * BM + rowA]      = av0[j];
            As[0][(colA4 + j) * BM + rowA + 64] = av1[j];
        }
        *reinterpret_cast<float4*>(&Bs[0][rowB * BN + colB4])       = b0;
        *reinterpret_cast<float4*>(&Bs[0][(rowB + 8) * BN + colB4]) = b1;
    }
    __syncthreads();

    #pragma unroll
    for (int it = 0; it < KQ / BK2; it++) {
        const int buf = it & 1;
        const bool more = (it + 1) < (KQ / BK2);
        if (more) {
            const int k0 = (it + 1) * BK2;
            a0 = *reinterpret_cast<const float4*>(gA0 + k0);
            a1 = *reinterpret_cast<const float4*>(gA1 + k0);
            b0 = *reinterpret_cast<const float4*>(gB0 + (size_t)k0 * NnB);
            b1 = *reinterpret_cast<const float4*>(gB1 + (size_t)k0 * NnB);
        }

        #pragma unroll
        for (int k = 0; k < BK2; k++) {
            const float4 m0 = *reinterpret_cast<const float4*>(
                &As[buf][k * BM + threadRow * TM]);
            const float4 m1 = *reinterpret_cast<const float4*>(
                &As[buf][k * BM + threadRow * TM + 4]);
            const uint64_t* bp = reinterpret_cast<const uint64_t*>(
                &Bs[buf][k * BN + threadCol * TN]);
            uint64_t bn[4];
            bn[0] = bp[0]; bn[1] = bp[1]; bn[2] = bp[2]; bn[3] = bp[3];

            const float mv[8] = {m0.x, m0.y, m0.z, m0.w, m1.x, m1.y, m1.z, m1.w};
            #pragma unroll
            for (int i = 0; i < TM; i++) {
                const uint32_t mu = __float_as_uint(mv[i]);
                uint64_t mm;
                asm("mov.b64 %0, {%1, %1};" : "=l"(mm) : "r"(mu));
                #pragma unroll
                for (int j2 = 0; j2 < TN / 2; j2++)
                    fma2(accp[i * (TN / 2) + j2], mm, bn[j2]);
            }
        }

        if (more) {
            const float av0[4] = {a0.x, a0.y, a0.z, a0.w};
            const float av1[4] = {a1.x, a1.y, a1.z, a1.w};
            #pragma unroll
            for (int j = 0; j < 4; j++) {
                As[buf ^ 1][(colA4 + j) * BM + rowA]      = av0[j];
                As[buf ^ 1][(colA4 + j) * BM + rowA + 64] = av1[j];
            }
            *reinterpret_cast<float4*>(&Bs[buf ^ 1][rowB * BN + colB4])       = b0;
            *reinterpret_cast<float4*>(&Bs[buf ^ 1][(rowB + 8) * BN + colB4]) = b1;
        }
        __syncthreads();
    }

    float bj[TN];
    #pragma unroll
    for (int j = 0; j < TN; j++)
        bj[j] = bias[colOff + threadCol * TN + j];

    #pragma unroll
    for (int i = 0; i < TM; i++) {
        const int row = crow * BM + threadRow * TM + i;
        float o[TN];
        #pragma unroll
        for (int j2 = 0; j2 < TN / 2; j2++) {
            uint32_t lo, hi;
            asm("mov.b64 {%0, %1}, %2;" : "=r"(lo), "=r"(hi)
                : "l"(accp[i * (TN / 2) + j2]));
            o[2 * j2]     = __uint_as_float(lo) + bj[2 * j2];
            o[2 * j2 + 1] = __uint_as_float(hi) + bj[2 * j2 + 1];
        }
        #pragma unroll
        for (int j = 0; j < TN; j += 4) {
            const int col = colOff + threadCol * TN + j;
            *reinterpret_cast<float4*>(&C[(size_t)row * NnC + col]) =
                make_float4(o[j], o[j + 1], o[j + 2], o[j + 3]);
        }
    }
}

// ---------------- device body: bf16x3 TC GEMM, cp.async 4-stage ---------------
#define GBK    32
#define GP     40
#define STAGES 4
#define OPELTS (128 * GP)
#define KSTEPS (KLOG3 / GBK)               // 24
#define GSMEM  (STAGES * 2 * OPELTS * 2)   // 81920 bytes

#define CP16(sm_, gp_) asm volatile( \
    "cp.async.cg.shared.global [%0], [%1], 16;" :: "r"(sm_), "l"(gp_))
#define CP_COMMIT()  asm volatile("cp.async.commit_group;")
#define CP_WAIT2()   asm volatile("cp.async.wait_group 2;")

// If Chalf != nullptr, write fp16 output there; else write fp32 to C.
__device__ __forceinline__
void tc_gemm_body(char* smemRaw, int m0, int n0, int Nn,
                  const __nv_bfloat16* __restrict__ A,
                  const __nv_bfloat16* __restrict__ Bt,
                  const float* __restrict__ bias,
                  float* __restrict__ C,
                  __half* __restrict__ Chalf)
{
    __nv_bfloat16* As_ = reinterpret_cast<__nv_bfloat16*>(smemRaw);
    __nv_bfloat16* Bs_ = As_ + STAGES * OPELTS;

    const int tid  = threadIdx.x;
    const int wid  = tid >> 5;
    const int lane = tid & 31;
    const int wm = (wid >> 2) * 64;
    const int wn = (wid & 3) * 32;
    const int g8  = lane >> 2;
    const int tig = lane & 3;

    const int lrow = tid >> 2;
    const int lseg = tid & 3;
    const __nv_bfloat16* gA0 = A  + (size_t)(m0 + lrow)      * K3 + lseg * 8;
    const __nv_bfloat16* gA1 = A  + (size_t)(m0 + lrow + 64) * K3 + lseg * 8;
    const __nv_bfloat16* gB0 = Bt + (size_t)(n0 + lrow)      * K3 + lseg * 8;
    const __nv_bfloat16* gB1 = Bt + (size_t)(n0 + lrow + 64) * K3 + lseg * 8;
    const uint32_t sA0 = (uint32_t)__cvta_generic_to_shared(
        &As_[lrow * GP + lseg * 8]);
    const uint32_t sB0 = (uint32_t)__cvta_generic_to_shared(
        &Bs_[lrow * GP + lseg * 8]);

    float c[4][4][4];
    #pragma unroll
    for (int mi = 0; mi < 4; mi++)
        #pragma unroll
        for (int ni = 0; ni < 4; ni++)
            #pragma unroll
            for (int r = 0; r < 4; r++) c[mi][ni][r] = 0.0f;

    auto load_stage = [&](int st) {
        const int slot = st & (STAGES - 1);
        const int k0   = st * GBK;
        const int seg  = k0 >> 8;
        const int ka   = c_amap[seg] * CCH + (k0 & 255);
        const int kb   = c_bmap[seg] * CCH + (k0 & 255);
        const uint32_t so = slot * OPELTS * 2;
        CP16(sA0 + so,               gA0 + ka);
        CP16(sA0 + so + 64 * GP * 2, gA1 + ka);
        CP16(sB0 + so,               gB0 + kb);
        CP16(sB0 + so + 64 * GP * 2, gB1 + kb);
    };

    load_stage(0); CP_COMMIT();
    load_stage(1); CP_COMMIT();
    load_stage(2); CP_COMMIT();

    for (int kt = 0; kt < KSTEPS; kt++) {
        CP_WAIT2();
        __syncthreads();
        const __nv_bfloat16* Asl = As_ + (kt & (STAGES - 1)) * OPELTS;
        const __nv_bfloat16* Bsl = Bs_ + (kt & (STAGES - 1)) * OPELTS;

        #pragma unroll
        for (int h = 0; h < 2; h++) {
            uint32_t afr[4][4], bfr[4][2];
            #pragma unroll
            for (int mi = 0; mi < 4; mi++) {
                const int rb = (wm + mi * 16 + g8) * GP + h * 16 + tig * 2;
                afr[mi][0] = *reinterpret_cast<const uint32_t*>(&Asl[rb]);
                afr[mi][1] = *reinterpret_cast<const uint32_t*>(&Asl[rb + 8 * GP]);
                afr[mi][2] = *reinterpret_cast<const uint32_t*>(&Asl[rb + 8]);
                afr[mi][3] = *reinterpret_cast<const uint32_t*>(&Asl[rb + 8 * GP + 8]);
            }
            #pragma unroll
            for (int ni = 0; ni < 4; ni++) {
                const int rb = (wn + ni * 8 + g8) * GP + h * 16 + tig * 2;
                bfr[ni][0] = *reinterpret_cast<const uint32_t*>(&Bsl[rb]);
                bfr[ni][1] = *reinterpret_cast<const uint32_t*>(&Bsl[rb + 8]);
            }
            #pragma unroll
            for (int mi = 0; mi < 4; mi++)
                #pragma unroll
                for (int ni = 0; ni < 4; ni++) {
                    asm volatile(
                        "mma.sync.aligned.m16n8k16.row.col.f32.bf16.bf16.f32 "
                        "{%0,%1,%2,%3}, {%4,%5,%6,%7}, {%8,%9}, {%0,%1,%2,%3};"
                        : "+f"(c[mi][ni][0]), "+f"(c[mi][ni][1]),
                          "+f"(c[mi][ni][2]), "+f"(c[mi][ni][3])
                        : "r"(afr[mi][0]), "r"(afr[mi][1]),
                          "r"(afr[mi][2]), "r"(afr[mi][3]),
                          "r"(bfr[ni][0]), "r"(bfr[ni][1]));
                }
        }

        if (kt + STAGES - 1 < KSTEPS) load_stage(kt + STAGES - 1);
        CP_COMMIT();
    }

    #pragma unroll
    for (int mi = 0; mi < 4; mi++) {
        const int row = m0 + wm + mi * 16 + g8;
        #pragma unroll
        for (int ni = 0; ni < 4; ni++) {
            const int col = n0 + wn + ni * 8 + tig * 2;
            const float b0 = bias[col], b1 = bias[col + 1];
            const float v00 = c[mi][ni][0] + b0, v01 = c[mi][ni][1] + b1;
            const float v10 = c[mi][ni][2] + b0, v11 = c[mi][ni][3] + b1;
            if (Chalf) {
                *reinterpret_cast<__half2*>(&Chalf[(size_t)row * Nn + col]) =
                    __floats2half2_rn(v00, v01);
                *reinterpret_cast<__half2*>(&Chalf[(size_t)(row + 8) * Nn + col]) =
                    __floats2half2_rn(v10, v11);
            } else {
                *reinterpret_cast<float2*>(&C[(size_t)row * Nn + col]) =
                    make_float2(v00, v01);
                *reinterpret_cast<float2*>(&C[(size_t)(row + 8) * Nn + col]) =
                    make_float2(v10, v11);
            }
        }
    }
}

// ---------------- mega kernel: TC value tiles + SIMT off/attn tiles ----------
__global__ __launch_bounds__(256)
void mega_gemm(const __nv_bfloat16* __restrict__ Ain,
               const __nv_bfloat16* __restrict__ Btv,
               const float* __restrict__ b_val,
               const float* __restrict__ query,
               const float* __restrict__ Boff,
               const float* __restrict__ Batt,
               const float* __restrict__ bias_off,
               const float* __restrict__ bias_att,
               float* __restrict__ Coff,
               float* __restrict__ Catt)
{
    extern __shared__ char smemRaw[];
    const int bid  = blockIdx.x;
    const int role = bid % 5;
    const int grp  = bid / 5;          // 0..169
    if (role < 2) {
        const int idx = grp * 2 + role;        // 0..339
        tc_gemm_body(smemRaw, (idx >> 1) * 128, (idx & 1) * 128, CCH,
                     Ain, Btv, b_val, nullptr, g_valueh);
    } else {
        const int idx = grp * 3 + (role - 2);  // 0..509
        simt_oa_body(smemRaw, idx / 3, idx % 3,
                     query, Boff, Batt, bias_off, bias_att, Coff, Catt);
    }
}

// ---------------- standalone TC GEMM (out projection, fp32 out) --------------
__global__ __launch_bounds__(256)
void gemm_bf16x3(int Nn,
                 const __nv_bfloat16* __restrict__ A,
                 const __nv_bfloat16* __restrict__ Bt,
                 const float* __restrict__ bias,
                 float* __restrict__ C)
{
    extern __shared__ char smemRaw[];
    tc_gemm_body(smemRaw, blockIdx.y * 128, blockIdx.x * 128, Nn,
                 A, Bt, bias, C, nullptr);
}

// ---------------- sampling: fp16 gathers, 8 queries/block --------------------
__global__ __launch_bounds__(256)
void sample_kernel(const float* __restrict__ refp)
{
    const int nq0 = blockIdx.x * QPB;
    const int tid = threadIdx.x;

    __shared__ float4 s_w[QPB * 128];
    __shared__ int4   s_t[QPB * 128];

    // ---------- phase 1: per (q,h,point) weights + indices ----------
    #pragma unroll
    for (int rep = 0; rep < QPB * 128 / 256; rep++) {   // 4 reps
        const int task = tid + rep * 256;
        const int q    = task >> 7;
        const int rest = task & 127;
        const int l    = (rest & 15) >> 2;
        const int nq   = nq0 + q;

        float logit = g_attn[(size_t)nq * 128 + rest];
        float mx = logit;
        #pragma unroll
        for (int m = 8; m; m >>= 1)
            mx = fmaxf(mx, __shfl_xor_sync(0xffffffffu, mx, m, 16));
        float e = __expf(logit - mx);
        float ssum = e;
        #pragma unroll
        for (int m = 8; m; m >>= 1)
            ssum += __shfl_xor_sync(0xffffffffu, ssum, m, 16);
        const float aw = e * (1.0f / ssum);

        const int W  = 64 >> l;
        const int S0 = (16384 - (16384 >> (2 * l))) / 3;

        const float2 off = *reinterpret_cast<const float2*>(
            &g_off[(size_t)nq * CCH + rest * 2]);
        const float2 rp  = *reinterpret_cast<const float2*>(
            &refp[((size_t)nq * NL + l) * 2]);

        const float locx = fminf(fmaxf(rp.x + off.x, 0.0f), 1.0f);
        const float locy = fminf(fmaxf(rp.y + off.y, 0.0f), 1.0f);
        const float x = locx * (float)W - 0.5f;
        const float y = locy * (float)W - 0.5f;
        const int xf = (int)floorf(x);
        const int yf = (int)floorf(y);
        const int x0i = min(max(xf,     0), W - 1);
        const int x1i = min(max(xf + 1, 0), W - 1);
        const int y0i = min(max(yf,     0), W - 1);
        const int y1i = min(max(yf + 1, 0), W - 1);
        const float wx1 = (float)x1i - x;
        const float wx0 = x - (float)x0i;
        const float wy1 = (float)y1i - y;
        const float wy0 = y - (float)y0i;

        s_w[task] = make_float4(wx1 * wy1 * aw, wx1 * wy0 * aw,
                                wx0 * wy1 * aw, wx0 * wy0 * aw);
        s_t[task] = make_int4(S0 + y0i * W + x0i,
                              S0 + y1i * W + x0i,
                              S0 + y0i * W + x1i,
                              S0 + y1i * W + x1i);
    }
    __syncthreads();

    // ---------- phase 2: fp16 gathers, 4 threads per (q,h), 8 halves each ----
    const int q  = tid >> 5;        // 0..7
    const int r  = tid & 31;
    const int h  = r >> 2;          // 0..7
    const int d8 = r & 3;           // 0..3 (8-half group)
    const int nq = nq0 + q;
    const int n  = nq / LQ;

    const __half* vb = g_valueh + (size_t)n * LEN_IN * CCH + h * DH + d8 * 8;

    float acc[8];
    #pragma unroll
    for (int j = 0; j < 8; j++) acc[j] = 0.0f;
    const int tb0 = q * 128 + h * 16;

    #pragma unroll
    for (int i = 0; i < 16; i++) {
        const float4 w  = s_w[tb0 + i];
        const int4   tt = s_t[tb0 + i];
        const uint4 ua = *reinterpret_cast<const uint4*>(vb + (size_t)tt.x * CCH);
        const uint4 ub = *reinterpret_cast<const uint4*>(vb + (size_t)tt.y * CCH);
        const uint4 uc = *reinterpret_cast<const uint4*>(vb + (size_t)tt.z * CCH);
        const uint4 ud = *reinterpret_cast<const uint4*>(vb + (size_t)tt.w * CCH);
        const __half2* ha = reinterpret_cast<const __half2*>(&ua);
        const __half2* hb = reinterpret_cast<const __half2*>(&ub);
        const __half2* hc = reinterpret_cast<const __half2*>(&uc);
        const __half2* hd = reinterpret_cast<const __half2*>(&ud);
        #pragma unroll
        for (int p = 0; p < 4; p++) {
            const float2 fa = __half22float2(ha[p]);
            const float2 fb = __half22float2(hb[p]);
            const float2 fc = __half22float2(hc[p]);
            const float2 fd = __half22float2(hd[p]);
            acc[2*p]   += w.x * fa.x + w.y * fb.x + w.z * fc.x + w.w * fd.x;
            acc[2*p+1] += w.x * fa.y + w.y * fb.y + w.z * fc.y + w.w * fd.y;
        }
    }

    // fused split (t0,t1 only — x3 out-GEMM never reads the t2 segment)
    __align__(8) __nv_bfloat16 t0[8], t1[8];
    #pragma unroll
    for (int j = 0; j < 8; j++) {
        t0[j] = __float2bfloat16(acc[j]);
        t1[j] = __float2bfloat16(acc[j] - __bfloat162float(t0[j]));
    }

    __nv_bfloat16* row = g_As + (size_t)nq * K3 + h * DH + d8 * 8;
    *reinterpret_cast<ushort4*>(row)           = *reinterpret_cast<ushort4*>(t0);
    *reinterpret_cast<ushort4*>(row + 4)       = *reinterpret_cast<ushort4*>(t0 + 4);
    *reinterpret_cast<ushort4*>(row + CCH)     = *reinterpret_cast<ushort4*>(t1);
    *reinterpret_cast<ushort4*>(row + CCH + 4) = *reinterpret_cast<ushort4*>(t1 + 4);
}

// ---------------- launch ------------------------------------------------------
extern "C" void kernel_launch(void* const* d_in, const int* in_sizes, int n_in,
                              void* d_out, int out_size)
{
    const float* query  = (const float*)d_in[0];
    const float* refp   = (const float*)d_in[1];
    const float* inputf = (const float*)d_in[2];
    const float* w_off  = (const float*)d_in[5];
    const float* b_off  = (const float*)d_in[6];
    const float* w_attn = (const float*)d_in[7];
    const float* b_attn = (const float*)d_in[8];
    const float* w_val  = (const float*)d_in[9];
    const float* b_val  = (const float*)d_in[10];
    const float* w_out  = (const float*)d_in[11];
    const float* b_out  = (const float*)d_in[12];
    float* out = (float*)d_out;

    cudaFuncSetAttribute(gemm_bf16x3,
                         cudaFuncAttributeMaxDynamicSharedMemorySize, GSMEM);
    cudaFuncSetAttribute(mega_gemm,
                         cudaFuncAttributeMaxDynamicSharedMemorySize, GSMEM);

    float *go, *ga;
    cudaGetSymbolAddress((void**)&go, g_off);
    cudaGetSymbolAddress((void**)&ga, g_attn);
    __nv_bfloat16 *ain, *as, *btv, *btw;
    cudaGetSymbolAddress((void**)&ain, g_Ain);
    cudaGetSymbolAddress((void**)&as,  g_As);
    cudaGetSymbolAddress((void**)&btv, g_Btv);
    cudaGetSymbolAddress((void**)&btw, g_Btw);

    const dim3 blk(256);
    const dim3 gSplitA(MROWS);
    const dim3 gGemm256(2, MROWS / 128);

    // splits for the TC GEMMs (value, out)
    split_weights<<<512, blk>>>(w_val, w_out);
    splitA_kernel<<<gSplitA, blk>>>(inputf, ain);

    // value (TC -> fp16 out) + off/attn (SIMT fp32 FFMA2) fused — pipe overlap
    mega_gemm<<<850, blk, GSMEM>>>(ain, btv, b_val,
                                   query, w_off, w_attn, b_off, b_attn, go, ga);

    // sampling (fp16 gathers) + fused split of sampled output
    sample_kernel<<<MROWS / QPB, blk>>>(refp);

    // out = samp @ w_out + b_out                  (TC bf16x3, fp32 out)
    gemm_bf16x3<<<gGemm256, blk, GSMEM>>>(CCH, as, btw, b_out, out);
}